// round 7
// baseline (speedup 1.0000x reference)
#include <cuda_runtime.h>
#include <math.h>

#define VOX   4096
#define TPTS  100
#define KNN   8

__device__ int g_perm[VOX];

// descending-nv permutation (LPT schedule). Single block; atomic scatter order
// varies but per-voxel output is order-independent => deterministic results.
__global__ void sort_kernel(const int* __restrict__ num_voxels) {
    __shared__ int s_cnt[101];
    __shared__ int s_off[101];
    const int tid = threadIdx.x;   // 1024
    if (tid < 101) s_cnt[tid] = 0;
    __syncthreads();
    for (int v = tid; v < VOX; v += 1024) {
        int nv = num_voxels[v];
        nv = nv < 1 ? 1 : (nv > 100 ? 100 : nv);
        atomicAdd(&s_cnt[nv], 1);
    }
    __syncthreads();
    if (tid == 0) {
        int acc = 0;
        for (int b = 100; b >= 1; b--) { s_off[b] = acc; acc += s_cnt[b]; }
    }
    __syncthreads();
    for (int v = tid; v < VOX; v += 1024) {
        int nv = num_voxels[v];
        nv = nv < 1 ? 1 : (nv > 100 ? 100 : nv);
        int pos = atomicAdd(&s_off[nv], 1);
        g_perm[pos] = v;
    }
}

// order-preserving float -> u32 (monotone increasing)
__device__ __forceinline__ unsigned ordf(float f) {
    unsigned u = __float_as_uint(f);
    unsigned m = (unsigned)((int)u >> 31);
    return u ^ (m | 0x80000000u);
}
// pack: top 25 key bits (rounded) | (127 - j)
__device__ __forceinline__ unsigned packkey(float key, int j) {
    unsigned u = ordf(key);
    return ((u + 0x40u) & 0xFFFFFF80u) | (unsigned)(127 - j);
}

// branchless top-8 insert on packed u32: 2 IMNMX per stage
__device__ __forceinline__ void ins8p(unsigned v[KNN], unsigned d) {
#pragma unroll
    for (int s = 0; s < KNN; s++) {
        unsigned vs = v[s];
        v[s] = vs > d ? vs : d;
        d    = vs > d ? d : vs;
    }
}

__device__ __forceinline__ unsigned long long fma_f32x2(
    unsigned long long a, unsigned long long b, unsigned long long c) {
    unsigned long long d;
    asm("fma.rn.f32x2 %0, %1, %2, %3;" : "=l"(d) : "l"(a), "l"(b), "l"(c));
    return d;
}
__device__ __forceinline__ unsigned long long pack2(float lo, float hi) {
    unsigned long long r;
    asm("mov.b64 %0, {%1, %2};" : "=l"(r) : "f"(lo), "f"(hi));
    return r;
}
__device__ __forceinline__ void unpack2(float& lo, float& hi, unsigned long long v) {
    asm("mov.b64 {%0, %1}, %2;" : "=f"(lo), "=f"(hi) : "l"(v));
}

__device__ __forceinline__ float4 lrelu4(float4 a, float4 b) {
    float4 h;
    h.x = a.x + b.x;  h.y = a.y + b.y;  h.z = a.z + b.z;  h.w = a.w + b.w;
    h.x = (h.x >= 0.f) ? h.x : 0.2f * h.x;
    h.y = (h.y >= 0.f) ? h.y : 0.2f * h.y;
    h.z = (h.z >= 0.f) ? h.z : 0.2f * h.z;
    h.w = (h.w >= 0.f) ? h.w : 0.2f * h.w;
    return h;
}

__global__ __launch_bounds__(128, 6) void gcn_kernel(
    const float* __restrict__ features,   // [4096,100,4]
    const float* __restrict__ conv_w,     // [64,18]
    const float* __restrict__ bn_gamma,
    const float* __restrict__ bn_beta,
    const float* __restrict__ bn_mean,
    const float* __restrict__ bn_var,
    const int*   __restrict__ num_voxels, // [4096]
    const int*   __restrict__ coors,      // [4096,4]
    float*       __restrict__ out)        // [4096,64]
{
    __shared__ __align__(16) float s_feat[TPTS][12];
    __shared__ __align__(16) float s_a[TPTS * 64];    // a'; overlaid w/ topk candidates
    __shared__ __align__(16) float s_wa[9 * 64];      // dead after phase 2 -> scr overlay
    __shared__ __align__(16) float s_wb[9 * 64];
    __shared__ __align__(16) float s_bias[64];
    __shared__ unsigned char s_idx[TPTS][KNN];
    __shared__ float s_red[16];
    __shared__ float s_mean[3];

    const int tid = threadIdx.x;
    const int vox = g_perm[blockIdx.x];
    int nv = num_voxels[vox];
    if (nv < 1) nv = 1;
    if (nv > TPTS) nv = TPTS;

    // ---- fold BN into weights ----
    if (tid < 64) {
        const int o = tid;
        float scale = bn_gamma[o] * rsqrtf(bn_var[o] + 1e-3f);
#pragma unroll
        for (int c = 0; c < 9; c++) {
            float w1 = conv_w[o * 18 + c];
            float w2 = conv_w[o * 18 + 9 + c];
            s_wa[c * 64 + o] = w1 * scale;
            s_wb[c * 64 + o] = (w2 - w1) * scale;
        }
        s_bias[o] = bn_beta[o] - bn_mean[o] * scale;
    }

    // ---- phase 1: load + mean over first 3 channels ----
    float4 fv = make_float4(0.f, 0.f, 0.f, 0.f);
    if (tid < TPTS)
        fv = reinterpret_cast<const float4*>(features)[vox * TPTS + tid];
    float sx = (tid < TPTS) ? fv.x : 0.f;
    float sy = (tid < TPTS) ? fv.y : 0.f;
    float sz = (tid < TPTS) ? fv.z : 0.f;
#pragma unroll
    for (int o = 16; o > 0; o >>= 1) {
        sx += __shfl_down_sync(0xffffffffu, sx, o);
        sy += __shfl_down_sync(0xffffffffu, sy, o);
        sz += __shfl_down_sync(0xffffffffu, sz, o);
    }
    if ((tid & 31) == 0) {
        int w = tid >> 5;
        s_red[w] = sx; s_red[4 + w] = sy; s_red[8 + w] = sz;
    }
    __syncthreads();
    if (tid == 0) {
        float fnv = (float)nv;
        s_mean[0] = (s_red[0] + s_red[1] + s_red[2] + s_red[3]) / fnv;
        s_mean[1] = (s_red[4] + s_red[5] + s_red[6] + s_red[7]) / fnv;
        s_mean[2] = (s_red[8] + s_red[9] + s_red[10] + s_red[11]) / fnv;
    }
    __syncthreads();

    const float cx = (float)coors[vox * 4 + 3] * 0.2f + 0.1f;
    const float cy = (float)coors[vox * 4 + 2] * 0.2f + (-39.9f);
    if (tid < TPTS) {
        float m = (tid < nv) ? 1.0f : 0.0f;
        float f[9];
        f[0] = fv.x * m;  f[1] = fv.y * m;  f[2] = fv.z * m;  f[3] = fv.w * m;
        f[4] = (fv.x - s_mean[0]) * m;
        f[5] = (fv.y - s_mean[1]) * m;
        f[6] = (fv.z - s_mean[2]) * m;
        f[7] = (fv.x - cx) * m;
        f[8] = (fv.y - cy) * m;
        float xx = 0.f;
#pragma unroll
        for (int c = 0; c < 9; c++) xx = fmaf(f[c], f[c], xx);
#pragma unroll
        for (int c = 0; c < 9; c++) s_feat[tid][c] = f[c];
        s_feat[tid][9]  = xx;
        s_feat[tid][10] = 0.f;
        s_feat[tid][11] = 0.f;
    }
    __syncthreads();

    // ---- phase 3: top-8 by key = <xt,xj> - xx_j/2 - xx_t/2; quarter-major ----
    unsigned* cand = reinterpret_cast<unsigned*>(s_a);  // [4*TPTS][8]
    const int nv2 = 2 * nv, nv3 = 3 * nv;
    const int items = 4 * nv;
    for (int it = tid; it < items; it += 128) {
        int q = (it >= nv) + (it >= nv2) + (it >= nv3);
        int t = it - q * nv;
        int j0 = (q * nv) >> 2;
        int j1 = ((q + 1) * nv) >> 2;

        const float4* fr = reinterpret_cast<const float4*>(s_feat[t]);
        float4 fa = fr[0], fb = fr[1];
        const float f8  = s_feat[t][8];
        const float xxh = -0.5f * s_feat[t][9];
        const unsigned long long fa01 = pack2(fa.x, fa.y);
        const unsigned long long fa23 = pack2(fa.z, fa.w);
        const unsigned long long fb01 = pack2(fb.x, fb.y);
        const unsigned long long fb23 = pack2(fb.z, fb.w);

        unsigned v[KNN];
#pragma unroll
        for (int k = 0; k < KNN; k++) v[k] = 0u;

#pragma unroll 2
        for (int j = j0; j < j1; j++) {
            const float* row = s_feat[j];
            const ulonglong2 jv = *reinterpret_cast<const ulonglong2*>(row);
            const ulonglong2 jw = *reinterpret_cast<const ulonglong2*>(row + 4);
            const float2 jc = *reinterpret_cast<const float2*>(row + 8);
            unsigned long long acc = fma_f32x2(fa01, jv.x, 0ull);
            acc = fma_f32x2(fa23, jv.y, acc);
            acc = fma_f32x2(fb01, jw.x, acc);
            acc = fma_f32x2(fb23, jw.y, acc);
            float lo, hi; unpack2(lo, hi, acc);
            float s = fmaf(-0.5f, jc.y, xxh);
            s = fmaf(f8, jc.x, s);
            float key = (lo + hi) + s;
            ins8p(v, packkey(key, j));
        }
#pragma unroll
        for (int k = 0; k < KNN; k++) cand[it * KNN + k] = v[k];
    }
    __syncthreads();

    // merge 4 quarter-lists, fill masked (key == -xx_t/2 exactly)
    if (tid < nv) {
        const int t = tid;
        unsigned v[KNN];
#pragma unroll
        for (int k = 0; k < KNN; k++) v[k] = cand[t * KNN + k];
#pragma unroll
        for (int k = 0; k < KNN; k++) ins8p(v, cand[(nv + t) * KNN + k]);
#pragma unroll
        for (int k = 0; k < KNN; k++) ins8p(v, cand[(nv2 + t) * KNN + k]);
#pragma unroll
        for (int k = 0; k < KNN; k++) ins8p(v, cand[(nv3 + t) * KNN + k]);
        const float mkey = -0.5f * s_feat[t][9];
        const unsigned mbase = (ordf(mkey) + 0x40u) & 0xFFFFFF80u;
        for (int jm = nv; jm < TPTS; jm++) {
            unsigned p = mbase | (unsigned)(127 - jm);
            if (!(p > v[KNN - 1])) break;
            ins8p(v, p);
        }
#pragma unroll
        for (int k = 0; k < KNN; k++)
            s_idx[t][k] = (unsigned char)(127u - (v[k] & 0x7Fu));
    }
    __syncthreads();

    // ---- phase 2: a' for rows t and t+50 per item (wa read once per pair) ----
    for (int p = tid; p < 50 * 16; p += 128) {
        int t  = p >> 4;          // 0..49
        int t2 = t + 50;
        int o4 = p & 15;
        const float4* f1 = reinterpret_cast<const float4*>(s_feat[t]);
        const float4* f2 = reinterpret_cast<const float4*>(s_feat[t2]);
        float4 a1 = f1[0], b1 = f1[1];
        float4 a2 = f2[0], b2 = f2[1];
        float fs1[9] = {a1.x, a1.y, a1.z, a1.w, b1.x, b1.y, b1.z, b1.w, s_feat[t][8]};
        float fs2[9] = {a2.x, a2.y, a2.z, a2.w, b2.x, b2.y, b2.z, b2.w, s_feat[t2][8]};
        float4 acc1 = make_float4(0.f, 0.f, 0.f, 0.f);
        float4 acc2 = make_float4(0.f, 0.f, 0.f, 0.f);
#pragma unroll
        for (int c = 0; c < 9; c++) {
            float4 wv = *reinterpret_cast<const float4*>(&s_wa[c * 64 + o4 * 4]);
            acc1.x = fmaf(fs1[c], wv.x, acc1.x);  acc2.x = fmaf(fs2[c], wv.x, acc2.x);
            acc1.y = fmaf(fs1[c], wv.y, acc1.y);  acc2.y = fmaf(fs2[c], wv.y, acc2.y);
            acc1.z = fmaf(fs1[c], wv.z, acc1.z);  acc2.z = fmaf(fs2[c], wv.z, acc2.z);
            acc1.w = fmaf(fs1[c], wv.w, acc1.w);  acc2.w = fmaf(fs2[c], wv.w, acc2.w);
        }
        reinterpret_cast<float4*>(s_a)[t  * 16 + o4] = acc1;
        reinterpret_cast<float4*>(s_a)[t2 * 16 + o4] = acc2;
    }
    __syncthreads();

    // ---- phase 4: two t's per iteration, wb/bias read once per pair ----
    float* s_scr = s_wa;   // dead -> scratch
    {
        const int o4    = tid & 15;
        const int slice = tid >> 4;   // 0..7
        float4 rmax = make_float4(0.f, 0.f, 0.f, 0.f);
        for (int t = slice; t < nv; t += 16) {
            int t2 = t + 8;
            int t2c = (t2 < nv) ? t2 : t;   // duplicate-safe: h2==h1 when clamped
            float4 m4a = make_float4(-3.402823466e38f, -3.402823466e38f,
                                     -3.402823466e38f, -3.402823466e38f);
            float4 m4b = m4a;
#pragma unroll
            for (int k = 0; k < KNN; k++) {
                int ja = (int)s_idx[t][k];
                int jb = (int)s_idx[t2c][k];
                float4 aa = reinterpret_cast<const float4*>(s_a)[ja * 16 + o4];
                float4 ab = reinterpret_cast<const float4*>(s_a)[jb * 16 + o4];
                m4a.x = fmaxf(m4a.x, aa.x);  m4b.x = fmaxf(m4b.x, ab.x);
                m4a.y = fmaxf(m4a.y, aa.y);  m4b.y = fmaxf(m4b.y, ab.y);
                m4a.z = fmaxf(m4a.z, aa.z);  m4b.z = fmaxf(m4b.z, ab.z);
                m4a.w = fmaxf(m4a.w, aa.w);  m4b.w = fmaxf(m4b.w, ab.w);
            }
            const float4* f1 = reinterpret_cast<const float4*>(s_feat[t]);
            const float4* f2 = reinterpret_cast<const float4*>(s_feat[t2c]);
            float4 a1 = f1[0], c1 = f1[1];
            float4 a2 = f2[0], c2 = f2[1];
            float fs1[9] = {a1.x, a1.y, a1.z, a1.w, c1.x, c1.y, c1.z, c1.w, s_feat[t][8]};
            float fs2[9] = {a2.x, a2.y, a2.z, a2.w, c2.x, c2.y, c2.z, c2.w, s_feat[t2c][8]};
            float4 bb = *reinterpret_cast<const float4*>(&s_bias[o4 * 4]);
            float4 b1 = bb, b2 = bb;
#pragma unroll
            for (int c = 0; c < 9; c++) {
                float4 wv = *reinterpret_cast<const float4*>(&s_wb[c * 64 + o4 * 4]);
                b1.x = fmaf(fs1[c], wv.x, b1.x);  b2.x = fmaf(fs2[c], wv.x, b2.x);
                b1.y = fmaf(fs1[c], wv.y, b1.y);  b2.y = fmaf(fs2[c], wv.y, b2.y);
                b1.z = fmaf(fs1[c], wv.z, b1.z);  b2.z = fmaf(fs2[c], wv.z, b2.z);
                b1.w = fmaf(fs1[c], wv.w, b1.w);  b2.w = fmaf(fs2[c], wv.w, b2.w);
            }
            float4 h1 = lrelu4(m4a, b1);
            float4 h2 = lrelu4(m4b, b2);
            rmax.x = fmaxf(rmax.x, fmaxf(h1.x, h2.x));
            rmax.y = fmaxf(rmax.y, fmaxf(h1.y, h2.y));
            rmax.z = fmaxf(rmax.z, fmaxf(h1.z, h2.z));
            rmax.w = fmaxf(rmax.w, fmaxf(h1.w, h2.w));
        }
        reinterpret_cast<float4*>(s_scr)[slice * 16 + o4] = rmax;
    }
    __syncthreads();

    if (tid < 64) {
        float r = s_scr[tid];
#pragma unroll
        for (int s = 1; s < 8; s++) r = fmaxf(r, s_scr[s * 64 + tid]);
        out[vox * 64 + tid] = r;
    }
}

extern "C" void kernel_launch(void* const* d_in, const int* in_sizes, int n_in,
                              void* d_out, int out_size) {
    const float* features   = (const float*)d_in[0];
    const float* conv_w     = (const float*)d_in[1];
    const float* bn_gamma   = (const float*)d_in[2];
    const float* bn_beta    = (const float*)d_in[3];
    const float* bn_mean    = (const float*)d_in[4];
    const float* bn_var     = (const float*)d_in[5];
    const int*   num_voxels = (const int*)d_in[6];
    const int*   coors      = (const int*)d_in[7];
    float*       out        = (float*)d_out;

    sort_kernel<<<1, 1024>>>(num_voxels);
    gcn_kernel<<<VOX, 128>>>(features, conv_w, bn_gamma, bn_beta, bn_mean, bn_var,
                             num_voxels, coors, out);
}

// round 8
// speedup vs baseline: 1.1654x; 1.1654x over previous
#include <cuda_runtime.h>
#include <math.h>

#define VOX   4096
#define TPTS  100
#define KNN   8

// order-preserving float -> u32 (monotone increasing)
__device__ __forceinline__ unsigned ordf(float f) {
    unsigned u = __float_as_uint(f);
    unsigned m = (unsigned)((int)u >> 31);
    return u ^ (m | 0x80000000u);
}
// pack: top 25 key bits (rounded) | (127 - j)
__device__ __forceinline__ unsigned packkey(float key, int j) {
    unsigned u = ordf(key);
    return ((u + 0x40u) & 0xFFFFFF80u) | (unsigned)(127 - j);
}

// branchless top-8 insert on packed u32: 2 IMNMX per stage
__device__ __forceinline__ void ins8p(unsigned v[KNN], unsigned d) {
#pragma unroll
    for (int s = 0; s < KNN; s++) {
        unsigned vs = v[s];
        v[s] = vs > d ? vs : d;
        d    = vs > d ? d : vs;
    }
}

__device__ __forceinline__ unsigned long long fma_f32x2(
    unsigned long long a, unsigned long long b, unsigned long long c) {
    unsigned long long d;
    asm("fma.rn.f32x2 %0, %1, %2, %3;" : "=l"(d) : "l"(a), "l"(b), "l"(c));
    return d;
}
__device__ __forceinline__ unsigned long long pack2(float lo, float hi) {
    unsigned long long r;
    asm("mov.b64 %0, {%1, %2};" : "=l"(r) : "f"(lo), "f"(hi));
    return r;
}
__device__ __forceinline__ void unpack2(float& lo, float& hi, unsigned long long v) {
    asm("mov.b64 {%0, %1}, %2;" : "=f"(lo), "=f"(hi) : "l"(v));
}

__device__ __forceinline__ float4 lrelu4(float4 a, float4 b) {
    float4 h;
    h.x = a.x + b.x;  h.y = a.y + b.y;  h.z = a.z + b.z;  h.w = a.w + b.w;
    h.x = (h.x >= 0.f) ? h.x : 0.2f * h.x;
    h.y = (h.y >= 0.f) ? h.y : 0.2f * h.y;
    h.z = (h.z >= 0.f) ? h.z : 0.2f * h.z;
    h.w = (h.w >= 0.f) ? h.w : 0.2f * h.w;
    return h;
}

// s_feat row (12 floats): [0..3]=(x,y,z,r)  [4..7]=(3x,3y,2z,r)
//                         [8]=-wxx/2  [9]=-xx9/2  [10,11]=pad
__global__ __launch_bounds__(128, 6) void gcn_kernel(
    const float* __restrict__ features,   // [4096,100,4]
    const float* __restrict__ conv_w,     // [64,18]
    const float* __restrict__ bn_gamma,
    const float* __restrict__ bn_beta,
    const float* __restrict__ bn_mean,
    const float* __restrict__ bn_var,
    const int*   __restrict__ num_voxels, // [4096]
    const int*   __restrict__ coors,      // [4096,4]
    float*       __restrict__ out)        // [4096,64]
{
    __shared__ __align__(16) float s_feat[TPTS][12];
    __shared__ __align__(16) float s_a[TPTS * 64];   // a'; overlaid w/ topk candidates
    __shared__ __align__(16) float s_wta[4 * 64];    // folded conv weights (a path)
    __shared__ __align__(16) float s_wtb[4 * 64];    // folded conv weights (b path)
    __shared__ __align__(16) float s_ca[64];         // const for a path
    __shared__ __align__(16) float s_cb[64];         // const + bias for b path
    __shared__ unsigned char s_idx[TPTS][KNN];
    __shared__ __align__(16) float s_scr[512];
    __shared__ float s_red[16];
    __shared__ float s_mean[3];

    const int tid = threadIdx.x;
    const int vox = blockIdx.x;
    int nv = num_voxels[vox];
    if (nv < 1) nv = 1;
    if (nv > TPTS) nv = TPTS;

    const float cx = (float)coors[vox * 4 + 3] * 0.2f + 0.1f;
    const float cy = (float)coors[vox * 4 + 2] * 0.2f + (-39.9f);

    // ---- phase 1a: load + mean over first 3 channels ----
    float4 fv = make_float4(0.f, 0.f, 0.f, 0.f);
    if (tid < TPTS)
        fv = reinterpret_cast<const float4*>(features)[vox * TPTS + tid];
    float sx = (tid < TPTS) ? fv.x : 0.f;
    float sy = (tid < TPTS) ? fv.y : 0.f;
    float sz = (tid < TPTS) ? fv.z : 0.f;
#pragma unroll
    for (int o = 16; o > 0; o >>= 1) {
        sx += __shfl_down_sync(0xffffffffu, sx, o);
        sy += __shfl_down_sync(0xffffffffu, sy, o);
        sz += __shfl_down_sync(0xffffffffu, sz, o);
    }
    if ((tid & 31) == 0) {
        int w = tid >> 5;
        s_red[w] = sx; s_red[4 + w] = sy; s_red[8 + w] = sz;
    }
    __syncthreads();
    if (tid == 0) {
        float fnv = (float)nv;
        s_mean[0] = (s_red[0] + s_red[1] + s_red[2] + s_red[3]) / fnv;
        s_mean[1] = (s_red[4] + s_red[5] + s_red[6] + s_red[7]) / fnv;
        s_mean[2] = (s_red[8] + s_red[9] + s_red[10] + s_red[11]) / fnv;
    }
    __syncthreads();

    const float mx = s_mean[0], my = s_mean[1], mz = s_mean[2];

    // ---- phase 1b: build rows ----
    if (tid < TPTS) {
        float m = (tid < nv) ? 1.0f : 0.0f;
        float x = fv.x, y = fv.y, z = fv.z, r = fv.w;
        float f[9];
        f[0] = x * m;  f[1] = y * m;  f[2] = z * m;  f[3] = r * m;
        f[4] = (x - mx) * m;
        f[5] = (y - my) * m;
        f[6] = (z - mz) * m;
        f[7] = (x - cx) * m;
        f[8] = (y - cy) * m;
        float xx9 = 0.f;
#pragma unroll
        for (int c = 0; c < 9; c++) xx9 = fmaf(f[c], f[c], xx9);
        float wxx = 3.f * x * x + 3.f * y * y + 2.f * z * z + r * r;
        float* row = s_feat[tid];
        row[0] = x;       row[1] = y;       row[2] = z;       row[3] = r;
        row[4] = 3.f * x; row[5] = 3.f * y; row[6] = 2.f * z; row[7] = r;
        row[8] = -0.5f * wxx;
        row[9] = -0.5f * xx9;
        row[10] = 0.f; row[11] = 0.f;
    }

    // ---- phase 1c: fold BN + m/c constants into 4-dim weights ----
    if (tid < 64) {
        const int o = tid;
        float scale = bn_gamma[o] * rsqrtf(bn_var[o] + 1e-3f);
        float w1[9], wd[9];
#pragma unroll
        for (int c = 0; c < 9; c++) {
            float a = conv_w[o * 18 + c] * scale;
            float b = conv_w[o * 18 + 9 + c] * scale;
            w1[c] = a;
            wd[c] = b - a;
        }
        s_wta[0 * 64 + o] = w1[0] + w1[4] + w1[7];
        s_wta[1 * 64 + o] = w1[1] + w1[5] + w1[8];
        s_wta[2 * 64 + o] = w1[2] + w1[6];
        s_wta[3 * 64 + o] = w1[3];
        s_ca[o] = -(mx * w1[4] + my * w1[5] + mz * w1[6] + cx * w1[7] + cy * w1[8]);
        s_wtb[0 * 64 + o] = wd[0] + wd[4] + wd[7];
        s_wtb[1 * 64 + o] = wd[1] + wd[5] + wd[8];
        s_wtb[2 * 64 + o] = wd[2] + wd[6];
        s_wtb[3 * 64 + o] = wd[3];
        s_cb[o] = -(mx * wd[4] + my * wd[5] + mz * wd[6] + cx * wd[7] + cy * wd[8])
                  + bn_beta[o] - bn_mean[o] * scale;
    }
    __syncthreads();

    // ---- phase 3: top-8 by key = pt.p~j - wxx_j/2 - wxx_t/2 (= -dist9^2/2) ----
    unsigned* cand = reinterpret_cast<unsigned*>(s_a);  // [4*TPTS][8]
    const int nv2 = 2 * nv, nv3 = 3 * nv;
    const int items = 4 * nv;
    for (int it = tid; it < items; it += 128) {
        int q = (it >= nv) + (it >= nv2) + (it >= nv3);
        int t = it - q * nv;
        int j0 = (q * nv) >> 2;
        int j1 = ((q + 1) * nv) >> 2;

        const float* trow = s_feat[t];
        const unsigned long long pa01 = pack2(trow[0], trow[1]);
        const unsigned long long pa23 = pack2(trow[2], trow[3]);
        const float xt_h = trow[8];

        unsigned v[KNN];
#pragma unroll
        for (int k = 0; k < KNN; k++) v[k] = 0u;

#pragma unroll 2
        for (int j = j0; j < j1; j++) {
            const float* row = s_feat[j];
            const ulonglong2 jb = *reinterpret_cast<const ulonglong2*>(row + 4);
            const float cj = row[8];
            unsigned long long acc = fma_f32x2(pa01, jb.x, 0ull);
            acc = fma_f32x2(pa23, jb.y, acc);
            float lo, hi; unpack2(lo, hi, acc);
            float key = (lo + hi) + (cj + xt_h);
            ins8p(v, packkey(key, j));
        }
#pragma unroll
        for (int k = 0; k < KNN; k++) cand[it * KNN + k] = v[k];
    }
    __syncthreads();

    // merge 4 quarter-lists, fill masked (key == -xx9_t/2 exactly)
    if (tid < nv) {
        const int t = tid;
        unsigned v[KNN];
#pragma unroll
        for (int k = 0; k < KNN; k++) v[k] = cand[t * KNN + k];
#pragma unroll
        for (int k = 0; k < KNN; k++) ins8p(v, cand[(nv + t) * KNN + k]);
#pragma unroll
        for (int k = 0; k < KNN; k++) ins8p(v, cand[(nv2 + t) * KNN + k]);
#pragma unroll
        for (int k = 0; k < KNN; k++) ins8p(v, cand[(nv3 + t) * KNN + k]);
        const float mkey = s_feat[t][9];
        const unsigned mbase = (ordf(mkey) + 0x40u) & 0xFFFFFF80u;
        for (int jm = nv; jm < TPTS; jm++) {
            unsigned p = mbase | (unsigned)(127 - jm);
            if (!(p > v[KNN - 1])) break;
            ins8p(v, p);
        }
#pragma unroll
        for (int k = 0; k < KNN; k++)
            s_idx[t][k] = (unsigned char)(127u - (v[k] & 0x7Fu));
    }
    __syncthreads();

    // ---- phase 2: a'[t] = m * (ca + p_t . wta), rows t and t+50 per item ----
    for (int p = tid; p < 50 * 16; p += 128) {
        int t  = p >> 4;          // 0..49
        int t2 = t + 50;
        int o4 = p & 15;
        float m1 = (t  < nv) ? 1.f : 0.f;
        float m2 = (t2 < nv) ? 1.f : 0.f;
        const float4 A1 = *reinterpret_cast<const float4*>(s_feat[t]);
        const float4 A2 = *reinterpret_cast<const float4*>(s_feat[t2]);
        float fs1[4] = {A1.x, A1.y, A1.z, A1.w};
        float fs2[4] = {A2.x, A2.y, A2.z, A2.w};
        float4 c4 = *reinterpret_cast<const float4*>(&s_ca[o4 * 4]);
        float4 acc1 = c4, acc2 = c4;
#pragma unroll
        for (int c = 0; c < 4; c++) {
            float4 wv = *reinterpret_cast<const float4*>(&s_wta[c * 64 + o4 * 4]);
            acc1.x = fmaf(fs1[c], wv.x, acc1.x);  acc2.x = fmaf(fs2[c], wv.x, acc2.x);
            acc1.y = fmaf(fs1[c], wv.y, acc1.y);  acc2.y = fmaf(fs2[c], wv.y, acc2.y);
            acc1.z = fmaf(fs1[c], wv.z, acc1.z);  acc2.z = fmaf(fs2[c], wv.z, acc2.z);
            acc1.w = fmaf(fs1[c], wv.w, acc1.w);  acc2.w = fmaf(fs2[c], wv.w, acc2.w);
        }
        acc1.x *= m1; acc1.y *= m1; acc1.z *= m1; acc1.w *= m1;
        acc2.x *= m2; acc2.y *= m2; acc2.z *= m2; acc2.w *= m2;
        reinterpret_cast<float4*>(s_a)[t  * 16 + o4] = acc1;
        reinterpret_cast<float4*>(s_a)[t2 * 16 + o4] = acc2;
    }
    __syncthreads();

    // ---- phase 4: two t's per iteration; b' = cb + p_t . wtb (t<nv => mask=1) ----
    {
        const int o4    = tid & 15;
        const int slice = tid >> 4;   // 0..7
        float4 rmax = make_float4(0.f, 0.f, 0.f, 0.f);
        for (int t = slice; t < nv; t += 16) {
            int t2 = t + 8;
            int t2c = (t2 < nv) ? t2 : t;   // duplicate-safe
            float4 m4a = make_float4(-3.402823466e38f, -3.402823466e38f,
                                     -3.402823466e38f, -3.402823466e38f);
            float4 m4b = m4a;
#pragma unroll
            for (int k = 0; k < KNN; k++) {
                int ja = (int)s_idx[t][k];
                int jb = (int)s_idx[t2c][k];
                float4 aa = reinterpret_cast<const float4*>(s_a)[ja * 16 + o4];
                float4 ab = reinterpret_cast<const float4*>(s_a)[jb * 16 + o4];
                m4a.x = fmaxf(m4a.x, aa.x);  m4b.x = fmaxf(m4b.x, ab.x);
                m4a.y = fmaxf(m4a.y, aa.y);  m4b.y = fmaxf(m4b.y, ab.y);
                m4a.z = fmaxf(m4a.z, aa.z);  m4b.z = fmaxf(m4b.z, ab.z);
                m4a.w = fmaxf(m4a.w, aa.w);  m4b.w = fmaxf(m4b.w, ab.w);
            }
            const float4 A1 = *reinterpret_cast<const float4*>(s_feat[t]);
            const float4 A2 = *reinterpret_cast<const float4*>(s_feat[t2c]);
            float fs1[4] = {A1.x, A1.y, A1.z, A1.w};
            float fs2[4] = {A2.x, A2.y, A2.z, A2.w};
            float4 cb4 = *reinterpret_cast<const float4*>(&s_cb[o4 * 4]);
            float4 b1 = cb4, b2 = cb4;
#pragma unroll
            for (int c = 0; c < 4; c++) {
                float4 wv = *reinterpret_cast<const float4*>(&s_wtb[c * 64 + o4 * 4]);
                b1.x = fmaf(fs1[c], wv.x, b1.x);  b2.x = fmaf(fs2[c], wv.x, b2.x);
                b1.y = fmaf(fs1[c], wv.y, b1.y);  b2.y = fmaf(fs2[c], wv.y, b2.y);
                b1.z = fmaf(fs1[c], wv.z, b1.z);  b2.z = fmaf(fs2[c], wv.z, b2.z);
                b1.w = fmaf(fs1[c], wv.w, b1.w);  b2.w = fmaf(fs2[c], wv.w, b2.w);
            }
            float4 h1 = lrelu4(m4a, b1);
            float4 h2 = lrelu4(m4b, b2);
            rmax.x = fmaxf(rmax.x, fmaxf(h1.x, h2.x));
            rmax.y = fmaxf(rmax.y, fmaxf(h1.y, h2.y));
            rmax.z = fmaxf(rmax.z, fmaxf(h1.z, h2.z));
            rmax.w = fmaxf(rmax.w, fmaxf(h1.w, h2.w));
        }
        reinterpret_cast<float4*>(s_scr)[slice * 16 + o4] = rmax;
    }
    __syncthreads();

    if (tid < 64) {
        float r = s_scr[tid];
#pragma unroll
        for (int s = 1; s < 8; s++) r = fmaxf(r, s_scr[s * 64 + tid]);
        out[vox * 64 + tid] = r;
    }
}

extern "C" void kernel_launch(void* const* d_in, const int* in_sizes, int n_in,
                              void* d_out, int out_size) {
    const float* features   = (const float*)d_in[0];
    const float* conv_w     = (const float*)d_in[1];
    const float* bn_gamma   = (const float*)d_in[2];
    const float* bn_beta    = (const float*)d_in[3];
    const float* bn_mean    = (const float*)d_in[4];
    const float* bn_var     = (const float*)d_in[5];
    const int*   num_voxels = (const int*)d_in[6];
    const int*   coors      = (const int*)d_in[7];
    float*       out        = (float*)d_out;

    gcn_kernel<<<VOX, 128>>>(features, conv_w, bn_gamma, bn_beta, bn_mean, bn_var,
                             num_voxels, coors, out);
}

// round 9
// speedup vs baseline: 1.2759x; 1.0948x over previous
#include <cuda_runtime.h>
#include <math.h>

#define VOX   4096
#define TPTS  100
#define KNN   8

// order-preserving float -> u32 (monotone increasing)
__device__ __forceinline__ unsigned ordf(float f) {
    unsigned u = __float_as_uint(f);
    unsigned m = (unsigned)((int)u >> 31);
    return u ^ (m | 0x80000000u);
}
// pack: top 25 key bits (rounded) | (127 - j)
__device__ __forceinline__ unsigned packkey(float key, int j) {
    unsigned u = ordf(key);
    return ((u + 0x40u) & 0xFFFFFF80u) | (unsigned)(127 - j);
}

// compare-exchange keeping max in a (desc order)
__device__ __forceinline__ void cswap(unsigned& a, unsigned& b) {
    unsigned mx = a > b ? a : b;
    unsigned mn = a > b ? b : a;
    a = mx; b = mn;
}

// sort a bitonic 8-sequence into descending order (12 comparators)
__device__ __forceinline__ void bitonic8(unsigned v[KNN]) {
    cswap(v[0], v[4]); cswap(v[1], v[5]); cswap(v[2], v[6]); cswap(v[3], v[7]);
    cswap(v[0], v[2]); cswap(v[1], v[3]); cswap(v[4], v[6]); cswap(v[5], v[7]);
    cswap(v[0], v[1]); cswap(v[2], v[3]); cswap(v[4], v[5]); cswap(v[6], v[7]);
}

// merge sorted-desc w[8] into sorted-desc v[8], keeping top-8 (32 IMNMX)
__device__ __forceinline__ void merge8(unsigned v[KNN], const unsigned w[KNN]) {
#pragma unroll
    for (int i = 0; i < KNN; i++) {
        unsigned b = w[KNN - 1 - i];
        v[i] = v[i] > b ? v[i] : b;
    }
    bitonic8(v);
}

// legacy single insert (used only for the short masked-fill loop)
__device__ __forceinline__ void ins8p(unsigned v[KNN], unsigned d) {
#pragma unroll
    for (int s = 0; s < KNN; s++) {
        unsigned vs = v[s];
        v[s] = vs > d ? vs : d;
        d    = vs > d ? d : vs;
    }
}

__device__ __forceinline__ unsigned long long fma_f32x2(
    unsigned long long a, unsigned long long b, unsigned long long c) {
    unsigned long long d;
    asm("fma.rn.f32x2 %0, %1, %2, %3;" : "=l"(d) : "l"(a), "l"(b), "l"(c));
    return d;
}
__device__ __forceinline__ unsigned long long pack2(float lo, float hi) {
    unsigned long long r;
    asm("mov.b64 %0, {%1, %2};" : "=l"(r) : "f"(lo), "f"(hi));
    return r;
}
__device__ __forceinline__ void unpack2(float& lo, float& hi, unsigned long long v) {
    asm("mov.b64 {%0, %1}, %2;" : "=f"(lo), "=f"(hi) : "l"(v));
}

__device__ __forceinline__ float4 lrelu4(float4 a, float4 b) {
    float4 h;
    h.x = a.x + b.x;  h.y = a.y + b.y;  h.z = a.z + b.z;  h.w = a.w + b.w;
    h.x = (h.x >= 0.f) ? h.x : 0.2f * h.x;
    h.y = (h.y >= 0.f) ? h.y : 0.2f * h.y;
    h.z = (h.z >= 0.f) ? h.z : 0.2f * h.z;
    h.w = (h.w >= 0.f) ? h.w : 0.2f * h.w;
    return h;
}

__device__ __forceinline__ unsigned keyat(const float (*s_feat)[12], int j,
                                          unsigned long long pa01,
                                          unsigned long long pa23, float xt_h) {
    const float* row = s_feat[j];
    const ulonglong2 jb = *reinterpret_cast<const ulonglong2*>(row + 4);
    const float cj = row[8];
    unsigned long long acc = fma_f32x2(pa01, jb.x, 0ull);
    acc = fma_f32x2(pa23, jb.y, acc);
    float lo, hi; unpack2(lo, hi, acc);
    float key = (lo + hi) + (cj + xt_h);
    return packkey(key, j);
}

// s_feat row (12 floats): [0..3]=(x,y,z,r)  [4..7]=(3x,3y,2z,r)
//                         [8]=-wxx/2  [9]=-xx9/2  [10,11]=pad
__global__ __launch_bounds__(128, 6) void gcn_kernel(
    const float* __restrict__ features,   // [4096,100,4]
    const float* __restrict__ conv_w,     // [64,18]
    const float* __restrict__ bn_gamma,
    const float* __restrict__ bn_beta,
    const float* __restrict__ bn_mean,
    const float* __restrict__ bn_var,
    const int*   __restrict__ num_voxels, // [4096]
    const int*   __restrict__ coors,      // [4096,4]
    float*       __restrict__ out)        // [4096,64]
{
    __shared__ __align__(16) float s_feat[TPTS][12];
    __shared__ __align__(16) float s_a[TPTS * 64];   // a'; overlaid w/ topk candidates
    __shared__ __align__(16) float s_wta[4 * 64];
    __shared__ __align__(16) float s_wtb[4 * 64];
    __shared__ __align__(16) float s_ca[64];
    __shared__ __align__(16) float s_cb[64];
    __shared__ unsigned char s_idx[TPTS][KNN];
    __shared__ __align__(16) float s_scr[512];
    __shared__ float s_red[16];
    __shared__ float s_mean[3];

    const int tid = threadIdx.x;
    const int vox = blockIdx.x;
    int nv = num_voxels[vox];
    if (nv < 1) nv = 1;
    if (nv > TPTS) nv = TPTS;

    const float cx = (float)coors[vox * 4 + 3] * 0.2f + 0.1f;
    const float cy = (float)coors[vox * 4 + 2] * 0.2f + (-39.9f);

    // ---- phase 1a: load + mean over first 3 channels ----
    float4 fv = make_float4(0.f, 0.f, 0.f, 0.f);
    if (tid < TPTS)
        fv = reinterpret_cast<const float4*>(features)[vox * TPTS + tid];
    float sx = (tid < TPTS) ? fv.x : 0.f;
    float sy = (tid < TPTS) ? fv.y : 0.f;
    float sz = (tid < TPTS) ? fv.z : 0.f;
#pragma unroll
    for (int o = 16; o > 0; o >>= 1) {
        sx += __shfl_down_sync(0xffffffffu, sx, o);
        sy += __shfl_down_sync(0xffffffffu, sy, o);
        sz += __shfl_down_sync(0xffffffffu, sz, o);
    }
    if ((tid & 31) == 0) {
        int w = tid >> 5;
        s_red[w] = sx; s_red[4 + w] = sy; s_red[8 + w] = sz;
    }
    __syncthreads();
    if (tid == 0) {
        float fnv = (float)nv;
        s_mean[0] = (s_red[0] + s_red[1] + s_red[2] + s_red[3]) / fnv;
        s_mean[1] = (s_red[4] + s_red[5] + s_red[6] + s_red[7]) / fnv;
        s_mean[2] = (s_red[8] + s_red[9] + s_red[10] + s_red[11]) / fnv;
    }
    __syncthreads();

    const float mx = s_mean[0], my = s_mean[1], mz = s_mean[2];

    // ---- phase 1b: build rows ----
    if (tid < TPTS) {
        float m = (tid < nv) ? 1.0f : 0.0f;
        float x = fv.x, y = fv.y, z = fv.z, r = fv.w;
        float f[9];
        f[0] = x * m;  f[1] = y * m;  f[2] = z * m;  f[3] = r * m;
        f[4] = (x - mx) * m;
        f[5] = (y - my) * m;
        f[6] = (z - mz) * m;
        f[7] = (x - cx) * m;
        f[8] = (y - cy) * m;
        float xx9 = 0.f;
#pragma unroll
        for (int c = 0; c < 9; c++) xx9 = fmaf(f[c], f[c], xx9);
        float wxx = 3.f * x * x + 3.f * y * y + 2.f * z * z + r * r;
        float* row = s_feat[tid];
        row[0] = x;       row[1] = y;       row[2] = z;       row[3] = r;
        row[4] = 3.f * x; row[5] = 3.f * y; row[6] = 2.f * z; row[7] = r;
        row[8] = -0.5f * wxx;
        row[9] = -0.5f * xx9;
        row[10] = 0.f; row[11] = 0.f;
    }

    // ---- phase 1c: fold BN + m/c constants into 4-dim weights ----
    if (tid < 64) {
        const int o = tid;
        float scale = bn_gamma[o] * rsqrtf(bn_var[o] + 1e-3f);
        float w1[9], wd[9];
#pragma unroll
        for (int c = 0; c < 9; c++) {
            float a = conv_w[o * 18 + c] * scale;
            float b = conv_w[o * 18 + 9 + c] * scale;
            w1[c] = a;
            wd[c] = b - a;
        }
        s_wta[0 * 64 + o] = w1[0] + w1[4] + w1[7];
        s_wta[1 * 64 + o] = w1[1] + w1[5] + w1[8];
        s_wta[2 * 64 + o] = w1[2] + w1[6];
        s_wta[3 * 64 + o] = w1[3];
        s_ca[o] = -(mx * w1[4] + my * w1[5] + mz * w1[6] + cx * w1[7] + cy * w1[8]);
        s_wtb[0 * 64 + o] = wd[0] + wd[4] + wd[7];
        s_wtb[1 * 64 + o] = wd[1] + wd[5] + wd[8];
        s_wtb[2 * 64 + o] = wd[2] + wd[6];
        s_wtb[3 * 64 + o] = wd[3];
        s_cb[o] = -(mx * wd[4] + my * wd[5] + mz * wd[6] + cx * wd[7] + cy * wd[8])
                  + bn_beta[o] - bn_mean[o] * scale;
    }
    __syncthreads();

    // ---- phase 3: top-8 scan with batch-4 bitonic network ----
    unsigned* cand = reinterpret_cast<unsigned*>(s_a);  // [4*TPTS][8]
    const int nv2 = 2 * nv, nv3 = 3 * nv;
    const int items = 4 * nv;
    for (int it = tid; it < items; it += 128) {
        int q = (it >= nv) + (it >= nv2) + (it >= nv3);
        int t = it - q * nv;
        int j0 = (q * nv) >> 2;
        int j1 = ((q + 1) * nv) >> 2;

        const float* trow = s_feat[t];
        const unsigned long long pa01 = pack2(trow[0], trow[1]);
        const unsigned long long pa23 = pack2(trow[2], trow[3]);
        const float xt_h = trow[8];

        unsigned v[KNN];
#pragma unroll
        for (int k = 0; k < KNN; k++) v[k] = 0u;

        for (int j = j0; j < j1; j += 4) {
            int r1 = (j + 1 < j1) ? j + 1 : j;
            int r2 = (j + 2 < j1) ? j + 2 : j;
            int r3 = (j + 3 < j1) ? j + 3 : j;
            unsigned d0 = keyat(s_feat, j, pa01, pa23, xt_h);
            unsigned d1 = keyat(s_feat, r1, pa01, pa23, xt_h);
            unsigned d2 = keyat(s_feat, r2, pa01, pa23, xt_h);
            unsigned d3 = keyat(s_feat, r3, pa01, pa23, xt_h);
            d1 = (j + 1 < j1) ? d1 : 0u;
            d2 = (j + 2 < j1) ? d2 : 0u;
            d3 = (j + 3 < j1) ? d3 : 0u;
            // sort 4 desc (5 comparators)
            cswap(d0, d1); cswap(d2, d3); cswap(d0, d2); cswap(d1, d3); cswap(d1, d2);
            // bitonic merge stage-1 vs sorted v (pads -inf for v[0..3] side)
            v[4] = v[4] > d3 ? v[4] : d3;
            v[5] = v[5] > d2 ? v[5] : d2;
            v[6] = v[6] > d1 ? v[6] : d1;
            v[7] = v[7] > d0 ? v[7] : d0;
            bitonic8(v);
        }
#pragma unroll
        for (int k = 0; k < KNN; k++) cand[it * KNN + k] = v[k];
    }
    __syncthreads();

    // ---- merge 4 quarter-lists with merge networks, fill masked ----
    if (tid < nv) {
        const int t = tid;
        unsigned v[KNN], w[KNN];
#pragma unroll
        for (int k = 0; k < KNN; k++) v[k] = cand[t * KNN + k];
#pragma unroll
        for (int k = 0; k < KNN; k++) w[k] = cand[(nv + t) * KNN + k];
        merge8(v, w);
#pragma unroll
        for (int k = 0; k < KNN; k++) w[k] = cand[(nv2 + t) * KNN + k];
        merge8(v, w);
#pragma unroll
        for (int k = 0; k < KNN; k++) w[k] = cand[(nv3 + t) * KNN + k];
        merge8(v, w);
        const float mkey = s_feat[t][9];
        const unsigned mbase = (ordf(mkey) + 0x40u) & 0xFFFFFF80u;
        for (int jm = nv; jm < TPTS; jm++) {
            unsigned p = mbase | (unsigned)(127 - jm);
            if (!(p > v[KNN - 1])) break;
            ins8p(v, p);
        }
#pragma unroll
        for (int k = 0; k < KNN; k++)
            s_idx[t][k] = (unsigned char)(127u - (v[k] & 0x7Fu));
    }
    __syncthreads();

    // ---- phase 2: a'[t] = m * (ca + p_t . wta), rows t and t+50 per item ----
    for (int p = tid; p < 50 * 16; p += 128) {
        int t  = p >> 4;
        int t2 = t + 50;
        int o4 = p & 15;
        float m1 = (t  < nv) ? 1.f : 0.f;
        float m2 = (t2 < nv) ? 1.f : 0.f;
        const float4 A1 = *reinterpret_cast<const float4*>(s_feat[t]);
        const float4 A2 = *reinterpret_cast<const float4*>(s_feat[t2]);
        float fs1[4] = {A1.x, A1.y, A1.z, A1.w};
        float fs2[4] = {A2.x, A2.y, A2.z, A2.w};
        float4 c4 = *reinterpret_cast<const float4*>(&s_ca[o4 * 4]);
        float4 acc1 = c4, acc2 = c4;
#pragma unroll
        for (int c = 0; c < 4; c++) {
            float4 wv = *reinterpret_cast<const float4*>(&s_wta[c * 64 + o4 * 4]);
            acc1.x = fmaf(fs1[c], wv.x, acc1.x);  acc2.x = fmaf(fs2[c], wv.x, acc2.x);
            acc1.y = fmaf(fs1[c], wv.y, acc1.y);  acc2.y = fmaf(fs2[c], wv.y, acc2.y);
            acc1.z = fmaf(fs1[c], wv.z, acc1.z);  acc2.z = fmaf(fs2[c], wv.z, acc2.z);
            acc1.w = fmaf(fs1[c], wv.w, acc1.w);  acc2.w = fmaf(fs2[c], wv.w, acc2.w);
        }
        acc1.x *= m1; acc1.y *= m1; acc1.z *= m1; acc1.w *= m1;
        acc2.x *= m2; acc2.y *= m2; acc2.z *= m2; acc2.w *= m2;
        reinterpret_cast<float4*>(s_a)[t  * 16 + o4] = acc1;
        reinterpret_cast<float4*>(s_a)[t2 * 16 + o4] = acc2;
    }
    __syncthreads();

    // ---- phase 4: two t's per iteration; b' = cb + p_t . wtb ----
    {
        const int o4    = tid & 15;
        const int slice = tid >> 4;
        float4 rmax = make_float4(0.f, 0.f, 0.f, 0.f);
        for (int t = slice; t < nv; t += 16) {
            int t2 = t + 8;
            int t2c = (t2 < nv) ? t2 : t;
            float4 m4a = make_float4(-3.402823466e38f, -3.402823466e38f,
                                     -3.402823466e38f, -3.402823466e38f);
            float4 m4b = m4a;
#pragma unroll
            for (int k = 0; k < KNN; k++) {
                int ja = (int)s_idx[t][k];
                int jb = (int)s_idx[t2c][k];
                float4 aa = reinterpret_cast<const float4*>(s_a)[ja * 16 + o4];
                float4 ab = reinterpret_cast<const float4*>(s_a)[jb * 16 + o4];
                m4a.x = fmaxf(m4a.x, aa.x);  m4b.x = fmaxf(m4b.x, ab.x);
                m4a.y = fmaxf(m4a.y, aa.y);  m4b.y = fmaxf(m4b.y, ab.y);
                m4a.z = fmaxf(m4a.z, aa.z);  m4b.z = fmaxf(m4b.z, ab.z);
                m4a.w = fmaxf(m4a.w, aa.w);  m4b.w = fmaxf(m4b.w, ab.w);
            }
            const float4 A1 = *reinterpret_cast<const float4*>(s_feat[t]);
            const float4 A2 = *reinterpret_cast<const float4*>(s_feat[t2c]);
            float fs1[4] = {A1.x, A1.y, A1.z, A1.w};
            float fs2[4] = {A2.x, A2.y, A2.z, A2.w};
            float4 cb4 = *reinterpret_cast<const float4*>(&s_cb[o4 * 4]);
            float4 b1 = cb4, b2 = cb4;
#pragma unroll
            for (int c = 0; c < 4; c++) {
                float4 wv = *reinterpret_cast<const float4*>(&s_wtb[c * 64 + o4 * 4]);
                b1.x = fmaf(fs1[c], wv.x, b1.x);  b2.x = fmaf(fs2[c], wv.x, b2.x);
                b1.y = fmaf(fs1[c], wv.y, b1.y);  b2.y = fmaf(fs2[c], wv.y, b2.y);
                b1.z = fmaf(fs1[c], wv.z, b1.z);  b2.z = fmaf(fs2[c], wv.z, b2.z);
                b1.w = fmaf(fs1[c], wv.w, b1.w);  b2.w = fmaf(fs2[c], wv.w, b2.w);
            }
            float4 h1 = lrelu4(m4a, b1);
            float4 h2 = lrelu4(m4b, b2);
            rmax.x = fmaxf(rmax.x, fmaxf(h1.x, h2.x));
            rmax.y = fmaxf(rmax.y, fmaxf(h1.y, h2.y));
            rmax.z = fmaxf(rmax.z, fmaxf(h1.z, h2.z));
            rmax.w = fmaxf(rmax.w, fmaxf(h1.w, h2.w));
        }
        reinterpret_cast<float4*>(s_scr)[slice * 16 + o4] = rmax;
    }
    __syncthreads();

    if (tid < 64) {
        float r = s_scr[tid];
#pragma unroll
        for (int s = 1; s < 8; s++) r = fmaxf(r, s_scr[s * 64 + tid]);
        out[vox * 64 + tid] = r;
    }
}

extern "C" void kernel_launch(void* const* d_in, const int* in_sizes, int n_in,
                              void* d_out, int out_size) {
    const float* features   = (const float*)d_in[0];
    const float* conv_w     = (const float*)d_in[1];
    const float* bn_gamma   = (const float*)d_in[2];
    const float* bn_beta    = (const float*)d_in[3];
    const float* bn_mean    = (const float*)d_in[4];
    const float* bn_var     = (const float*)d_in[5];
    const int*   num_voxels = (const int*)d_in[6];
    const int*   coors      = (const int*)d_in[7];
    float*       out        = (float*)d_out;

    gcn_kernel<<<VOX, 128>>>(features, conv_w, bn_gamma, bn_beta, bn_mean, bn_var,
                             num_voxels, coors, out);
}

// round 10
// speedup vs baseline: 1.2934x; 1.0137x over previous
#include <cuda_runtime.h>
#include <math.h>

#define VOX   4096
#define TPTS  100
#define KNN   8

// order-preserving float -> u32 (monotone increasing)
__device__ __forceinline__ unsigned ordf(float f) {
    unsigned u = __float_as_uint(f);
    unsigned m = (unsigned)((int)u >> 31);
    return u ^ (m | 0x80000000u);
}
// pack: top 25 key bits (truncated) | (127 - j)
__device__ __forceinline__ unsigned packkey(float key, int j) {
    return (ordf(key) & 0xFFFFFF80u) | (unsigned)(127 - j);
}

__device__ __forceinline__ void cswap(unsigned& a, unsigned& b) {
    unsigned mx = a > b ? a : b;
    unsigned mn = a > b ? b : a;
    a = mx; b = mn;
}

// sort a bitonic 8-sequence into descending order (12 comparators)
__device__ __forceinline__ void bitonic8(unsigned v[KNN]) {
    cswap(v[0], v[4]); cswap(v[1], v[5]); cswap(v[2], v[6]); cswap(v[3], v[7]);
    cswap(v[0], v[2]); cswap(v[1], v[3]); cswap(v[4], v[6]); cswap(v[5], v[7]);
    cswap(v[0], v[1]); cswap(v[2], v[3]); cswap(v[4], v[5]); cswap(v[6], v[7]);
}

// merge sorted-desc w[8] into sorted-desc v[8], keeping top-8
__device__ __forceinline__ void merge8(unsigned v[KNN], const unsigned w[KNN]) {
#pragma unroll
    for (int i = 0; i < KNN; i++) {
        unsigned b = w[KNN - 1 - i];
        v[i] = v[i] > b ? v[i] : b;
    }
    bitonic8(v);
}

// single insert (short masked-fill loop only)
__device__ __forceinline__ void ins8p(unsigned v[KNN], unsigned d) {
#pragma unroll
    for (int s = 0; s < KNN; s++) {
        unsigned vs = v[s];
        v[s] = vs > d ? vs : d;
        d    = vs > d ? d : vs;
    }
}

__device__ __forceinline__ unsigned long long fma_f32x2(
    unsigned long long a, unsigned long long b, unsigned long long c) {
    unsigned long long d;
    asm("fma.rn.f32x2 %0, %1, %2, %3;" : "=l"(d) : "l"(a), "l"(b), "l"(c));
    return d;
}
__device__ __forceinline__ unsigned long long pack2(float lo, float hi) {
    unsigned long long r;
    asm("mov.b64 %0, {%1, %2};" : "=l"(r) : "f"(lo), "f"(hi));
    return r;
}
__device__ __forceinline__ void unpack2(float& lo, float& hi, unsigned long long v) {
    asm("mov.b64 {%0, %1}, %2;" : "=f"(lo), "=f"(hi) : "l"(v));
}

__device__ __forceinline__ float4 lrelu4(float4 a, float4 b) {
    float4 h;
    h.x = a.x + b.x;  h.y = a.y + b.y;  h.z = a.z + b.z;  h.w = a.w + b.w;
    h.x = (h.x >= 0.f) ? h.x : 0.2f * h.x;
    h.y = (h.y >= 0.f) ? h.y : 0.2f * h.y;
    h.z = (h.z >= 0.f) ? h.z : 0.2f * h.z;
    h.w = (h.w >= 0.f) ? h.w : 0.2f * h.w;
    return h;
}

// s_feat row (12 floats): [0..3]=(x,y,z,r)  [4..7]=(3x,3y,2z,r)
//                         [8]=-wxx/2 (-inf on masked/pad rows)  [9]=-xx9/2
__global__ __launch_bounds__(128, 6) void gcn_kernel(
    const float* __restrict__ features,   // [4096,100,4]
    const float* __restrict__ conv_w,     // [64,18]
    const float* __restrict__ bn_gamma,
    const float* __restrict__ bn_beta,
    const float* __restrict__ bn_mean,
    const float* __restrict__ bn_var,
    const int*   __restrict__ num_voxels, // [4096]
    const int*   __restrict__ coors,      // [4096,4]
    float*       __restrict__ out)        // [4096,64]
{
    __shared__ __align__(16) float s_feat[TPTS + 4][12];
    __shared__ __align__(16) float s_a[TPTS * 64];   // a'; overlaid w/ topk candidates
    __shared__ __align__(16) float s_wta[4 * 64];
    __shared__ __align__(16) float s_wtb[4 * 64];
    __shared__ __align__(16) float s_ca[64];
    __shared__ __align__(16) float s_cb[64];
    __shared__ unsigned char s_idx[TPTS][KNN];
    __shared__ __align__(16) float s_scr[512];
    __shared__ float s_red[16];
    __shared__ float s_mean[3];

    const int tid  = threadIdx.x;
    const int warp = tid >> 5;
    const int lane = tid & 31;
    const int vox  = blockIdx.x;
    int nv = num_voxels[vox];
    if (nv < 1) nv = 1;
    if (nv > TPTS) nv = TPTS;

    const float cx = (float)coors[vox * 4 + 3] * 0.2f + 0.1f;
    const float cy = (float)coors[vox * 4 + 2] * 0.2f + (-39.9f);

    // ---- phase 1a: load + mean over first 3 channels (raw, over all T) ----
    float4 fv = make_float4(0.f, 0.f, 0.f, 0.f);
    if (tid < TPTS)
        fv = reinterpret_cast<const float4*>(features)[vox * TPTS + tid];
    float sx = (tid < TPTS) ? fv.x : 0.f;
    float sy = (tid < TPTS) ? fv.y : 0.f;
    float sz = (tid < TPTS) ? fv.z : 0.f;
#pragma unroll
    for (int o = 16; o > 0; o >>= 1) {
        sx += __shfl_down_sync(0xffffffffu, sx, o);
        sy += __shfl_down_sync(0xffffffffu, sy, o);
        sz += __shfl_down_sync(0xffffffffu, sz, o);
    }
    if (lane == 0) {
        s_red[warp] = sx; s_red[4 + warp] = sy; s_red[8 + warp] = sz;
    }
    __syncthreads();
    if (tid == 0) {
        float fnv = (float)nv;
        s_mean[0] = (s_red[0] + s_red[1] + s_red[2] + s_red[3]) / fnv;
        s_mean[1] = (s_red[4] + s_red[5] + s_red[6] + s_red[7]) / fnv;
        s_mean[2] = (s_red[8] + s_red[9] + s_red[10] + s_red[11]) / fnv;
    }
    __syncthreads();

    const float mx = s_mean[0], my = s_mean[1], mz = s_mean[2];

    // ---- phase 1b: build rows; masked (t>=nv) and pad rows get key -inf ----
    if (tid < TPTS + 4) {
        float* row = s_feat[tid];
        if (tid < nv) {
            float x = fv.x, y = fv.y, z = fv.z, r = fv.w;
            float f[9];
            f[0] = x;  f[1] = y;  f[2] = z;  f[3] = r;
            f[4] = x - mx;  f[5] = y - my;  f[6] = z - mz;
            f[7] = x - cx;  f[8] = y - cy;
            float xx9 = 0.f;
#pragma unroll
            for (int c = 0; c < 9; c++) xx9 = fmaf(f[c], f[c], xx9);
            float wxx = 3.f * x * x + 3.f * y * y + 2.f * z * z + r * r;
            row[0] = x;       row[1] = y;       row[2] = z;       row[3] = r;
            row[4] = 3.f * x; row[5] = 3.f * y; row[6] = 2.f * z; row[7] = r;
            row[8] = -0.5f * wxx;
            row[9] = -0.5f * xx9;
            row[10] = 0.f; row[11] = 0.f;
        } else {
#pragma unroll
            for (int c = 0; c < 12; c++) row[c] = 0.f;
            row[8] = -__int_as_float(0x7F800000);   // -inf => key -inf, never kept
        }
    }

    // ---- phase 1c: fold BN + m/c constants into 4-dim weights ----
    if (tid < 64) {
        const int o = tid;
        float scale = bn_gamma[o] * rsqrtf(bn_var[o] + 1e-3f);
        float w1[9], wd[9];
#pragma unroll
        for (int c = 0; c < 9; c++) {
            float a = conv_w[o * 18 + c] * scale;
            float b = conv_w[o * 18 + 9 + c] * scale;
            w1[c] = a;
            wd[c] = b - a;
        }
        s_wta[0 * 64 + o] = w1[0] + w1[4] + w1[7];
        s_wta[1 * 64 + o] = w1[1] + w1[5] + w1[8];
        s_wta[2 * 64 + o] = w1[2] + w1[6];
        s_wta[3 * 64 + o] = w1[3];
        s_ca[o] = -(mx * w1[4] + my * w1[5] + mz * w1[6] + cx * w1[7] + cy * w1[8]);
        s_wtb[0 * 64 + o] = wd[0] + wd[4] + wd[7];
        s_wtb[1 * 64 + o] = wd[1] + wd[5] + wd[8];
        s_wtb[2 * 64 + o] = wd[2] + wd[6];
        s_wtb[3 * 64 + o] = wd[3];
        s_cb[o] = -(mx * wd[4] + my * wd[5] + mz * wd[6] + cx * wd[7] + cy * wd[8])
                  + bn_beta[o] - bn_mean[o] * scale;
    }
    __syncthreads();

    // ---- phase 3: warp w owns 4-aligned j-range [b_w, b_{w+1}); lanes stride t.
    //      All lanes of a warp scan the SAME j (broadcast), no tail guards. ----
    unsigned* cand = reinterpret_cast<unsigned*>(s_a);  // [4*TPTS][8]
    const int b0 = 4 * ((warp * nv) >> 4);
    const int b1 = (warp == 3) ? 4 * ((nv + 3) >> 2) : 4 * (((warp + 1) * nv) >> 4);

    for (int t = lane; t < nv; t += 32) {
        const float* trow = s_feat[t];
        const unsigned long long pa01 = pack2(trow[0], trow[1]);
        const unsigned long long pa23 = pack2(trow[2], trow[3]);
        const float xt_h = trow[8];

        unsigned v[KNN];
#pragma unroll
        for (int k = 0; k < KNN; k++) v[k] = 0u;

        for (int j = b0; j < b1; j += 4) {
            unsigned d[4];
#pragma unroll
            for (int u = 0; u < 4; u++) {
                const float* row = s_feat[j + u];
                const ulonglong2 jb = *reinterpret_cast<const ulonglong2*>(row + 4);
                const float cj = row[8];
                unsigned long long acc = fma_f32x2(pa01, jb.x, 0ull);
                acc = fma_f32x2(pa23, jb.y, acc);
                float lo, hi; unpack2(lo, hi, acc);
                float key = (lo + hi) + (cj + xt_h);
                d[u] = packkey(key, j + u);
            }
            // sort 4 desc (5 comparators)
            cswap(d[0], d[1]); cswap(d[2], d[3]);
            cswap(d[0], d[2]); cswap(d[1], d[3]); cswap(d[1], d[2]);
            // bitonic merge stage-1 vs sorted v, then cleanup
            v[4] = v[4] > d[3] ? v[4] : d[3];
            v[5] = v[5] > d[2] ? v[5] : d[2];
            v[6] = v[6] > d[1] ? v[6] : d[1];
            v[7] = v[7] > d[0] ? v[7] : d[0];
            bitonic8(v);
        }
#pragma unroll
        for (int k = 0; k < KNN; k++) cand[(warp * nv + t) * KNN + k] = v[k];
    }
    __syncthreads();

    // ---- merge 4 warp-lists, fill masked analytically (key == -xx9_t/2) ----
    if (tid < nv) {
        const int t = tid;
        const int nv2 = 2 * nv, nv3 = 3 * nv;
        unsigned v[KNN], w[KNN];
#pragma unroll
        for (int k = 0; k < KNN; k++) v[k] = cand[t * KNN + k];
#pragma unroll
        for (int k = 0; k < KNN; k++) w[k] = cand[(nv + t) * KNN + k];
        merge8(v, w);
#pragma unroll
        for (int k = 0; k < KNN; k++) w[k] = cand[(nv2 + t) * KNN + k];
        merge8(v, w);
#pragma unroll
        for (int k = 0; k < KNN; k++) w[k] = cand[(nv3 + t) * KNN + k];
        merge8(v, w);
        const float mkey = s_feat[t][9];
        const unsigned mbase = ordf(mkey) & 0xFFFFFF80u;
        for (int jm = nv; jm < TPTS; jm++) {
            unsigned p = mbase | (unsigned)(127 - jm);
            if (!(p > v[KNN - 1])) break;
            ins8p(v, p);
        }
#pragma unroll
        for (int k = 0; k < KNN; k++)
            s_idx[t][k] = (unsigned char)(127u - (v[k] & 0x7Fu));
    }
    __syncthreads();

    // ---- phase 2: a'[t] = mask * (ca + p_t . wta) (masked rows are zero => ca*0) ----
    for (int p = tid; p < 50 * 16; p += 128) {
        int t  = p >> 4;
        int t2 = t + 50;
        int o4 = p & 15;
        float m1 = (t  < nv) ? 1.f : 0.f;
        float m2 = (t2 < nv) ? 1.f : 0.f;
        const float4 A1 = *reinterpret_cast<const float4*>(s_feat[t]);
        const float4 A2 = *reinterpret_cast<const float4*>(s_feat[t2]);
        float fs1[4] = {A1.x, A1.y, A1.z, A1.w};
        float fs2[4] = {A2.x, A2.y, A2.z, A2.w};
        float4 c4 = *reinterpret_cast<const float4*>(&s_ca[o4 * 4]);
        float4 acc1 = c4, acc2 = c4;
#pragma unroll
        for (int c = 0; c < 4; c++) {
            float4 wv = *reinterpret_cast<const float4*>(&s_wta[c * 64 + o4 * 4]);
            acc1.x = fmaf(fs1[c], wv.x, acc1.x);  acc2.x = fmaf(fs2[c], wv.x, acc2.x);
            acc1.y = fmaf(fs1[c], wv.y, acc1.y);  acc2.y = fmaf(fs2[c], wv.y, acc2.y);
            acc1.z = fmaf(fs1[c], wv.z, acc1.z);  acc2.z = fmaf(fs2[c], wv.z, acc2.z);
            acc1.w = fmaf(fs1[c], wv.w, acc1.w);  acc2.w = fmaf(fs2[c], wv.w, acc2.w);
        }
        acc1.x *= m1; acc1.y *= m1; acc1.z *= m1; acc1.w *= m1;
        acc2.x *= m2; acc2.y *= m2; acc2.z *= m2; acc2.w *= m2;
        reinterpret_cast<float4*>(s_a)[t  * 16 + o4] = acc1;
        reinterpret_cast<float4*>(s_a)[t2 * 16 + o4] = acc2;
    }
    __syncthreads();

    // ---- phase 4: two t's per iteration; b' = cb + p_t . wtb ----
    {
        const int o4    = tid & 15;
        const int slice = tid >> 4;
        float4 rmax = make_float4(0.f, 0.f, 0.f, 0.f);
        for (int t = slice; t < nv; t += 16) {
            int t2 = t + 8;
            int t2c = (t2 < nv) ? t2 : t;
            float4 m4a = make_float4(-3.402823466e38f, -3.402823466e38f,
                                     -3.402823466e38f, -3.402823466e38f);
            float4 m4b = m4a;
#pragma unroll
            for (int k = 0; k < KNN; k++) {
                int ja = (int)s_idx[t][k];
                int jb = (int)s_idx[t2c][k];
                float4 aa = reinterpret_cast<const float4*>(s_a)[ja * 16 + o4];
                float4 ab = reinterpret_cast<const float4*>(s_a)[jb * 16 + o4];
                m4a.x = fmaxf(m4a.x, aa.x);  m4b.x = fmaxf(m4b.x, ab.x);
                m4a.y = fmaxf(m4a.y, aa.y);  m4b.y = fmaxf(m4b.y, ab.y);
                m4a.z = fmaxf(m4a.z, aa.z);  m4b.z = fmaxf(m4b.z, ab.z);
                m4a.w = fmaxf(m4a.w, aa.w);  m4b.w = fmaxf(m4b.w, ab.w);
            }
            const float4 A1 = *reinterpret_cast<const float4*>(s_feat[t]);
            const float4 A2 = *reinterpret_cast<const float4*>(s_feat[t2c]);
            float fs1[4] = {A1.x, A1.y, A1.z, A1.w};
            float fs2[4] = {A2.x, A2.y, A2.z, A2.w};
            float4 cb4 = *reinterpret_cast<const float4*>(&s_cb[o4 * 4]);
            float4 b1 = cb4, b2 = cb4;
#pragma unroll
            for (int c = 0; c < 4; c++) {
                float4 wv = *reinterpret_cast<const float4*>(&s_wtb[c * 64 + o4 * 4]);
                b1.x = fmaf(fs1[c], wv.x, b1.x);  b2.x = fmaf(fs2[c], wv.x, b2.x);
                b1.y = fmaf(fs1[c], wv.y, b1.y);  b2.y = fmaf(fs2[c], wv.y, b2.y);
                b1.z = fmaf(fs1[c], wv.z, b1.z);  b2.z = fmaf(fs2[c], wv.z, b2.z);
                b1.w = fmaf(fs1[c], wv.w, b1.w);  b2.w = fmaf(fs2[c], wv.w, b2.w);
            }
            float4 h1 = lrelu4(m4a, b1);
            float4 h2 = lrelu4(m4b, b2);
            rmax.x = fmaxf(rmax.x, fmaxf(h1.x, h2.x));
            rmax.y = fmaxf(rmax.y, fmaxf(h1.y, h2.y));
            rmax.z = fmaxf(rmax.z, fmaxf(h1.z, h2.z));
            rmax.w = fmaxf(rmax.w, fmaxf(h1.w, h2.w));
        }
        reinterpret_cast<float4*>(s_scr)[slice * 16 + o4] = rmax;
    }
    __syncthreads();

    if (tid < 64) {
        float r = s_scr[tid];
#pragma unroll
        for (int s = 1; s < 8; s++) r = fmaxf(r, s_scr[s * 64 + tid]);
        out[vox * 64 + tid] = r;
    }
}

extern "C" void kernel_launch(void* const* d_in, const int* in_sizes, int n_in,
                              void* d_out, int out_size) {
    const float* features   = (const float*)d_in[0];
    const float* conv_w     = (const float*)d_in[1];
    const float* bn_gamma   = (const float*)d_in[2];
    const float* bn_beta    = (const float*)d_in[3];
    const float* bn_mean    = (const float*)d_in[4];
    const float* bn_var     = (const float*)d_in[5];
    const int*   num_voxels = (const int*)d_in[6];
    const int*   coors      = (const int*)d_in[7];
    float*       out        = (float*)d_out;

    gcn_kernel<<<VOX, 128>>>(features, conv_w, bn_gamma, bn_beta, bn_mean, bn_var,
                             num_voxels, coors, out);
}

// round 11
// speedup vs baseline: 1.3981x; 1.0810x over previous
#include <cuda_runtime.h>
#include <cuda_fp16.h>
#include <math.h>

#define VOX   4096
#define TPTS  100
#define KNN   8

// order-preserving float -> u32 (monotone increasing)
__device__ __forceinline__ unsigned ordf(float f) {
    unsigned u = __float_as_uint(f);
    unsigned m = (unsigned)((int)u >> 31);
    return u ^ (m | 0x80000000u);
}
// pack: top 25 key bits (truncated) | (127 - j)
__device__ __forceinline__ unsigned packkey(float key, int j) {
    return (ordf(key) & 0xFFFFFF80u) | (unsigned)(127 - j);
}

__device__ __forceinline__ void cswap(unsigned& a, unsigned& b) {
    unsigned mx = a > b ? a : b;
    unsigned mn = a > b ? b : a;
    a = mx; b = mn;
}

// sort a bitonic 8-sequence into descending order (12 comparators)
__device__ __forceinline__ void bitonic8(unsigned v[KNN]) {
    cswap(v[0], v[4]); cswap(v[1], v[5]); cswap(v[2], v[6]); cswap(v[3], v[7]);
    cswap(v[0], v[2]); cswap(v[1], v[3]); cswap(v[4], v[6]); cswap(v[5], v[7]);
    cswap(v[0], v[1]); cswap(v[2], v[3]); cswap(v[4], v[5]); cswap(v[6], v[7]);
}

// merge sorted-desc w[8] into sorted-desc v[8], keeping top-8
__device__ __forceinline__ void merge8(unsigned v[KNN], const unsigned w[KNN]) {
#pragma unroll
    for (int i = 0; i < KNN; i++) {
        unsigned b = w[KNN - 1 - i];
        v[i] = v[i] > b ? v[i] : b;
    }
    bitonic8(v);
}

// single insert (short masked-fill loop only)
__device__ __forceinline__ void ins8p(unsigned v[KNN], unsigned d) {
#pragma unroll
    for (int s = 0; s < KNN; s++) {
        unsigned vs = v[s];
        v[s] = vs > d ? vs : d;
        d    = vs > d ? d : vs;
    }
}

__device__ __forceinline__ unsigned long long fma_f32x2(
    unsigned long long a, unsigned long long b, unsigned long long c) {
    unsigned long long d;
    asm("fma.rn.f32x2 %0, %1, %2, %3;" : "=l"(d) : "l"(a), "l"(b), "l"(c));
    return d;
}
__device__ __forceinline__ unsigned long long pack2(float lo, float hi) {
    unsigned long long r;
    asm("mov.b64 %0, {%1, %2};" : "=l"(r) : "f"(lo), "f"(hi));
    return r;
}
__device__ __forceinline__ void unpack2(float& lo, float& hi, unsigned long long v) {
    asm("mov.b64 {%0, %1}, %2;" : "=f"(lo), "=f"(hi) : "l"(v));
}

__device__ __forceinline__ float4 lrelu4(float4 a, float4 b) {
    float4 h;
    h.x = a.x + b.x;  h.y = a.y + b.y;  h.z = a.z + b.z;  h.w = a.w + b.w;
    h.x = (h.x >= 0.f) ? h.x : 0.2f * h.x;
    h.y = (h.y >= 0.f) ? h.y : 0.2f * h.y;
    h.z = (h.z >= 0.f) ? h.z : 0.2f * h.z;
    h.w = (h.w >= 0.f) ? h.w : 0.2f * h.w;
    return h;
}

// s_feat row (12 floats): [0..3]=(x,y,z,r)  [4..7]=(3x,3y,2z,r)
//                         [8]=-wxx/2 (-inf on masked/pad rows)  [9]=-xx9/2
__global__ __launch_bounds__(128, 9) void gcn_kernel(
    const float* __restrict__ features,   // [4096,100,4]
    const float* __restrict__ conv_w,     // [64,18]
    const float* __restrict__ bn_gamma,
    const float* __restrict__ bn_beta,
    const float* __restrict__ bn_mean,
    const float* __restrict__ bn_var,
    const int*   __restrict__ num_voxels, // [4096]
    const int*   __restrict__ coors,      // [4096,4]
    float*       __restrict__ out)        // [4096,64]
{
    __shared__ __align__(16) float s_feat[TPTS + 4][12];
    // 12.8 KB buffer: phase 3 = candidate lists (u32[4*TPTS][8]),
    //                 phase 2/4 = a' in fp16 (__half2[TPTS][32])
    __shared__ __align__(16) unsigned s_ab[TPTS * 32];
    __shared__ __align__(16) float s_wta[4 * 64];
    __shared__ __align__(16) float s_wtb[4 * 64];
    __shared__ __align__(16) float s_ca[64];
    __shared__ __align__(16) float s_cb[64];
    __shared__ unsigned char s_idx[TPTS][KNN];
    __shared__ __align__(16) float s_scr[512];
    __shared__ float s_red[16];
    __shared__ float s_mean[3];

    const int tid  = threadIdx.x;
    const int warp = tid >> 5;
    const int lane = tid & 31;
    const int vox  = blockIdx.x;
    int nv = num_voxels[vox];
    if (nv < 1) nv = 1;
    if (nv > TPTS) nv = TPTS;

    const float cx = (float)coors[vox * 4 + 3] * 0.2f + 0.1f;
    const float cy = (float)coors[vox * 4 + 2] * 0.2f + (-39.9f);

    // ---- phase 1a: load + mean over first 3 channels ----
    float4 fv = make_float4(0.f, 0.f, 0.f, 0.f);
    if (tid < TPTS)
        fv = reinterpret_cast<const float4*>(features)[vox * TPTS + tid];
    float sx = (tid < TPTS) ? fv.x : 0.f;
    float sy = (tid < TPTS) ? fv.y : 0.f;
    float sz = (tid < TPTS) ? fv.z : 0.f;
#pragma unroll
    for (int o = 16; o > 0; o >>= 1) {
        sx += __shfl_down_sync(0xffffffffu, sx, o);
        sy += __shfl_down_sync(0xffffffffu, sy, o);
        sz += __shfl_down_sync(0xffffffffu, sz, o);
    }
    if (lane == 0) {
        s_red[warp] = sx; s_red[4 + warp] = sy; s_red[8 + warp] = sz;
    }
    __syncthreads();
    if (tid == 0) {
        float fnv = (float)nv;
        s_mean[0] = (s_red[0] + s_red[1] + s_red[2] + s_red[3]) / fnv;
        s_mean[1] = (s_red[4] + s_red[5] + s_red[6] + s_red[7]) / fnv;
        s_mean[2] = (s_red[8] + s_red[9] + s_red[10] + s_red[11]) / fnv;
    }
    __syncthreads();

    const float mx = s_mean[0], my = s_mean[1], mz = s_mean[2];

    // ---- phase 1b: build rows; masked (t>=nv) and pad rows get key -inf ----
    if (tid < TPTS + 4) {
        float* row = s_feat[tid];
        if (tid < nv) {
            float x = fv.x, y = fv.y, z = fv.z, r = fv.w;
            float f[9];
            f[0] = x;  f[1] = y;  f[2] = z;  f[3] = r;
            f[4] = x - mx;  f[5] = y - my;  f[6] = z - mz;
            f[7] = x - cx;  f[8] = y - cy;
            float xx9 = 0.f;
#pragma unroll
            for (int c = 0; c < 9; c++) xx9 = fmaf(f[c], f[c], xx9);
            float wxx = 3.f * x * x + 3.f * y * y + 2.f * z * z + r * r;
            row[0] = x;       row[1] = y;       row[2] = z;       row[3] = r;
            row[4] = 3.f * x; row[5] = 3.f * y; row[6] = 2.f * z; row[7] = r;
            row[8] = -0.5f * wxx;
            row[9] = -0.5f * xx9;
            row[10] = 0.f; row[11] = 0.f;
        } else {
#pragma unroll
            for (int c = 0; c < 12; c++) row[c] = 0.f;
            row[8] = -__int_as_float(0x7F800000);   // -inf key, never kept
        }
    }

    // ---- phase 1c: fold BN + m/c constants into 4-dim weights ----
    if (tid < 64) {
        const int o = tid;
        float scale = bn_gamma[o] * rsqrtf(bn_var[o] + 1e-3f);
        float w1[9], wd[9];
#pragma unroll
        for (int c = 0; c < 9; c++) {
            float a = conv_w[o * 18 + c] * scale;
            float b = conv_w[o * 18 + 9 + c] * scale;
            w1[c] = a;
            wd[c] = b - a;
        }
        s_wta[0 * 64 + o] = w1[0] + w1[4] + w1[7];
        s_wta[1 * 64 + o] = w1[1] + w1[5] + w1[8];
        s_wta[2 * 64 + o] = w1[2] + w1[6];
        s_wta[3 * 64 + o] = w1[3];
        s_ca[o] = -(mx * w1[4] + my * w1[5] + mz * w1[6] + cx * w1[7] + cy * w1[8]);
        s_wtb[0 * 64 + o] = wd[0] + wd[4] + wd[7];
        s_wtb[1 * 64 + o] = wd[1] + wd[5] + wd[8];
        s_wtb[2 * 64 + o] = wd[2] + wd[6];
        s_wtb[3 * 64 + o] = wd[3];
        s_cb[o] = -(mx * wd[4] + my * wd[5] + mz * wd[6] + cx * wd[7] + cy * wd[8])
                  + bn_beta[o] - bn_mean[o] * scale;
    }
    __syncthreads();

    // ---- phase 3: warp w owns 4-aligned j-range; lanes stride t (broadcast j) ----
    unsigned* cand = s_ab;  // [4*nv][8] fits: 4*100*8 = 3200 u32
    const int b0 = 4 * ((warp * nv) >> 4);
    const int b1 = (warp == 3) ? 4 * ((nv + 3) >> 2) : 4 * (((warp + 1) * nv) >> 4);

    for (int t = lane; t < nv; t += 32) {
        const float* trow = s_feat[t];
        const unsigned long long pa01 = pack2(trow[0], trow[1]);
        const unsigned long long pa23 = pack2(trow[2], trow[3]);
        const float xt_h = trow[8];

        unsigned v[KNN];
#pragma unroll
        for (int k = 0; k < KNN; k++) v[k] = 0u;

        for (int j = b0; j < b1; j += 4) {
            unsigned d[4];
#pragma unroll
            for (int u = 0; u < 4; u++) {
                const float* row = s_feat[j + u];
                const ulonglong2 jb = *reinterpret_cast<const ulonglong2*>(row + 4);
                const float cj = row[8];
                unsigned long long acc = fma_f32x2(pa01, jb.x, 0ull);
                acc = fma_f32x2(pa23, jb.y, acc);
                float lo, hi; unpack2(lo, hi, acc);
                float key = (lo + hi) + (cj + xt_h);
                d[u] = packkey(key, j + u);
            }
            cswap(d[0], d[1]); cswap(d[2], d[3]);
            cswap(d[0], d[2]); cswap(d[1], d[3]); cswap(d[1], d[2]);
            v[4] = v[4] > d[3] ? v[4] : d[3];
            v[5] = v[5] > d[2] ? v[5] : d[2];
            v[6] = v[6] > d[1] ? v[6] : d[1];
            v[7] = v[7] > d[0] ? v[7] : d[0];
            bitonic8(v);
        }
#pragma unroll
        for (int k = 0; k < KNN; k++) cand[(warp * nv + t) * KNN + k] = v[k];
    }
    __syncthreads();

    // ---- merge 4 warp-lists, fill masked analytically ----
    if (tid < nv) {
        const int t = tid;
        const int nv2 = 2 * nv, nv3 = 3 * nv;
        unsigned v[KNN], w[KNN];
#pragma unroll
        for (int k = 0; k < KNN; k++) v[k] = cand[t * KNN + k];
#pragma unroll
        for (int k = 0; k < KNN; k++) w[k] = cand[(nv + t) * KNN + k];
        merge8(v, w);
#pragma unroll
        for (int k = 0; k < KNN; k++) w[k] = cand[(nv2 + t) * KNN + k];
        merge8(v, w);
#pragma unroll
        for (int k = 0; k < KNN; k++) w[k] = cand[(nv3 + t) * KNN + k];
        merge8(v, w);
        const float mkey = s_feat[t][9];
        const unsigned mbase = ordf(mkey) & 0xFFFFFF80u;
        for (int jm = nv; jm < TPTS; jm++) {
            unsigned p = mbase | (unsigned)(127 - jm);
            if (!(p > v[KNN - 1])) break;
            ins8p(v, p);
        }
#pragma unroll
        for (int k = 0; k < KNN; k++)
            s_idx[t][k] = (unsigned char)(127u - (v[k] & 0x7Fu));
    }
    __syncthreads();

    // ---- phase 2: a'[t] = mask*(ca + p_t . wta) -> fp16x2 (overwrites cand) ----
    __half2* a16 = reinterpret_cast<__half2*>(s_ab);   // [TPTS][32] half2
    for (int p = tid; p < 50 * 16; p += 128) {
        int t  = p >> 4;
        int t2 = t + 50;
        int o4 = p & 15;
        float m1 = (t  < nv) ? 1.f : 0.f;
        float m2 = (t2 < nv) ? 1.f : 0.f;
        const float4 A1 = *reinterpret_cast<const float4*>(s_feat[t]);
        const float4 A2 = *reinterpret_cast<const float4*>(s_feat[t2]);
        float fs1[4] = {A1.x, A1.y, A1.z, A1.w};
        float fs2[4] = {A2.x, A2.y, A2.z, A2.w};
        float4 c4 = *reinterpret_cast<const float4*>(&s_ca[o4 * 4]);
        float4 acc1 = c4, acc2 = c4;
#pragma unroll
        for (int c = 0; c < 4; c++) {
            float4 wv = *reinterpret_cast<const float4*>(&s_wta[c * 64 + o4 * 4]);
            acc1.x = fmaf(fs1[c], wv.x, acc1.x);  acc2.x = fmaf(fs2[c], wv.x, acc2.x);
            acc1.y = fmaf(fs1[c], wv.y, acc1.y);  acc2.y = fmaf(fs2[c], wv.y, acc2.y);
            acc1.z = fmaf(fs1[c], wv.z, acc1.z);  acc2.z = fmaf(fs2[c], wv.z, acc2.z);
            acc1.w = fmaf(fs1[c], wv.w, acc1.w);  acc2.w = fmaf(fs2[c], wv.w, acc2.w);
        }
        acc1.x *= m1; acc1.y *= m1; acc1.z *= m1; acc1.w *= m1;
        acc2.x *= m2; acc2.y *= m2; acc2.z *= m2; acc2.w *= m2;
        a16[t  * 32 + o4 * 2]     = __floats2half2_rn(acc1.x, acc1.y);
        a16[t  * 32 + o4 * 2 + 1] = __floats2half2_rn(acc1.z, acc1.w);
        a16[t2 * 32 + o4 * 2]     = __floats2half2_rn(acc2.x, acc2.y);
        a16[t2 * 32 + o4 * 2 + 1] = __floats2half2_rn(acc2.z, acc2.w);
    }
    __syncthreads();

    // ---- phase 4: fp16 gather-max (hmax2), fp32 b' + lrelu; two t's per iter ----
    {
        const int o4    = tid & 15;
        const int slice = tid >> 4;
        const __half2 hneg = __float2half2_rn(-60000.f);
        float4 rmax = make_float4(0.f, 0.f, 0.f, 0.f);
        for (int t = slice; t < nv; t += 16) {
            int t2 = t + 8;
            int t2c = (t2 < nv) ? t2 : t;
            __half2 ma0 = hneg, ma1 = hneg, mb0 = hneg, mb1 = hneg;
#pragma unroll
            for (int k = 0; k < KNN; k++) {
                int ja = (int)s_idx[t][k];
                int jb = (int)s_idx[t2c][k];
                __half2 a0 = a16[ja * 32 + o4 * 2];
                __half2 a1 = a16[ja * 32 + o4 * 2 + 1];
                __half2 b0 = a16[jb * 32 + o4 * 2];
                __half2 b1 = a16[jb * 32 + o4 * 2 + 1];
                ma0 = __hmax2(ma0, a0);  ma1 = __hmax2(ma1, a1);
                mb0 = __hmax2(mb0, b0);  mb1 = __hmax2(mb1, b1);
            }
            float2 fa0 = __half22float2(ma0), fa1 = __half22float2(ma1);
            float2 fb0 = __half22float2(mb0), fb1 = __half22float2(mb1);
            float4 m4a = make_float4(fa0.x, fa0.y, fa1.x, fa1.y);
            float4 m4b = make_float4(fb0.x, fb0.y, fb1.x, fb1.y);

            const float4 A1 = *reinterpret_cast<const float4*>(s_feat[t]);
            const float4 A2 = *reinterpret_cast<const float4*>(s_feat[t2c]);
            float fs1[4] = {A1.x, A1.y, A1.z, A1.w};
            float fs2[4] = {A2.x, A2.y, A2.z, A2.w};
            float4 cb4 = *reinterpret_cast<const float4*>(&s_cb[o4 * 4]);
            float4 b1 = cb4, b2 = cb4;
#pragma unroll
            for (int c = 0; c < 4; c++) {
                float4 wv = *reinterpret_cast<const float4*>(&s_wtb[c * 64 + o4 * 4]);
                b1.x = fmaf(fs1[c], wv.x, b1.x);  b2.x = fmaf(fs2[c], wv.x, b2.x);
                b1.y = fmaf(fs1[c], wv.y, b1.y);  b2.y = fmaf(fs2[c], wv.y, b2.y);
                b1.z = fmaf(fs1[c], wv.z, b1.z);  b2.z = fmaf(fs2[c], wv.z, b2.z);
                b1.w = fmaf(fs1[c], wv.w, b1.w);  b2.w = fmaf(fs2[c], wv.w, b2.w);
            }
            float4 h1 = lrelu4(m4a, b1);
            float4 h2 = lrelu4(m4b, b2);
            rmax.x = fmaxf(rmax.x, fmaxf(h1.x, h2.x));
            rmax.y = fmaxf(rmax.y, fmaxf(h1.y, h2.y));
            rmax.z = fmaxf(rmax.z, fmaxf(h1.z, h2.z));
            rmax.w = fmaxf(rmax.w, fmaxf(h1.w, h2.w));
        }
        reinterpret_cast<float4*>(s_scr)[slice * 16 + o4] = rmax;
    }
    __syncthreads();

    if (tid < 64) {
        float r = s_scr[tid];
#pragma unroll
        for (int s = 1; s < 8; s++) r = fmaxf(r, s_scr[s * 64 + tid]);
        out[vox * 64 + tid] = r;
    }
}

extern "C" void kernel_launch(void* const* d_in, const int* in_sizes, int n_in,
                              void* d_out, int out_size) {
    const float* features   = (const float*)d_in[0];
    const float* conv_w     = (const float*)d_in[1];
    const float* bn_gamma   = (const float*)d_in[2];
    const float* bn_beta    = (const float*)d_in[3];
    const float* bn_mean    = (const float*)d_in[4];
    const float* bn_var     = (const float*)d_in[5];
    const int*   num_voxels = (const int*)d_in[6];
    const int*   coors      = (const int*)d_in[7];
    float*       out        = (float*)d_out;

    gcn_kernel<<<VOX, 128>>>(features, conv_w, bn_gamma, bn_beta, bn_mean, bn_var,
                             num_voxels, coors, out);
}

// round 12
// speedup vs baseline: 1.4530x; 1.0393x over previous
#include <cuda_runtime.h>
#include <cuda_fp16.h>
#include <math.h>

#define VOX   4096
#define TPTS  100
#define KNN   8

// order-preserving float -> u32 (monotone increasing)
__device__ __forceinline__ unsigned ordf(float f) {
    unsigned u = __float_as_uint(f);
    unsigned m = (unsigned)((int)u >> 31);
    return u ^ (m | 0x80000000u);
}
// pack: top 25 key bits (truncated) | (127 - j)
__device__ __forceinline__ unsigned packkey(float key, int j) {
    return (ordf(key) & 0xFFFFFF80u) | (unsigned)(127 - j);
}

__device__ __forceinline__ void cswap(unsigned& a, unsigned& b) {
    unsigned mx = a > b ? a : b;
    unsigned mn = a > b ? b : a;
    a = mx; b = mn;
}

// sort a bitonic 8-sequence into descending order (12 comparators)
__device__ __forceinline__ void bitonic8(unsigned v[KNN]) {
    cswap(v[0], v[4]); cswap(v[1], v[5]); cswap(v[2], v[6]); cswap(v[3], v[7]);
    cswap(v[0], v[2]); cswap(v[1], v[3]); cswap(v[4], v[6]); cswap(v[5], v[7]);
    cswap(v[0], v[1]); cswap(v[2], v[3]); cswap(v[4], v[5]); cswap(v[6], v[7]);
}

// merge sorted-desc w[8] into sorted-desc v[8], keeping top-8
__device__ __forceinline__ void merge8(unsigned v[KNN], const unsigned w[KNN]) {
#pragma unroll
    for (int i = 0; i < KNN; i++) {
        unsigned b = w[KNN - 1 - i];
        v[i] = v[i] > b ? v[i] : b;
    }
    bitonic8(v);
}

// single insert (short masked-fill loop only)
__device__ __forceinline__ void ins8p(unsigned v[KNN], unsigned d) {
#pragma unroll
    for (int s = 0; s < KNN; s++) {
        unsigned vs = v[s];
        v[s] = vs > d ? vs : d;
        d    = vs > d ? d : vs;
    }
}

__device__ __forceinline__ unsigned long long fma_f32x2(
    unsigned long long a, unsigned long long b, unsigned long long c) {
    unsigned long long d;
    asm("fma.rn.f32x2 %0, %1, %2, %3;" : "=l"(d) : "l"(a), "l"(b), "l"(c));
    return d;
}
__device__ __forceinline__ unsigned long long pack2(float lo, float hi) {
    unsigned long long r;
    asm("mov.b64 %0, {%1, %2};" : "=l"(r) : "f"(lo), "f"(hi));
    return r;
}
__device__ __forceinline__ void unpack2(float& lo, float& hi, unsigned long long v) {
    asm("mov.b64 {%0, %1}, %2;" : "=f"(lo), "=f"(hi) : "l"(v));
}

__device__ __forceinline__ float4 lrelu4(float4 a, float4 b) {
    float4 h;
    h.x = a.x + b.x;  h.y = a.y + b.y;  h.z = a.z + b.z;  h.w = a.w + b.w;
    h.x = (h.x >= 0.f) ? h.x : 0.2f * h.x;
    h.y = (h.y >= 0.f) ? h.y : 0.2f * h.y;
    h.z = (h.z >= 0.f) ? h.z : 0.2f * h.z;
    h.w = (h.w >= 0.f) ? h.w : 0.2f * h.w;
    return h;
}

// s_feat row (12 floats): [0..3]=(x,y,z,r)  [4..7]=(3x,3y,2z,r)
//                         [8]=-wxx/2 (-inf on masked/pad rows)  [9]=-xx9/2
__global__ __launch_bounds__(128, 9) void gcn_kernel(
    const float* __restrict__ features,   // [4096,100,4]
    const float* __restrict__ conv_w,     // [64,18]
    const float* __restrict__ bn_gamma,
    const float* __restrict__ bn_beta,
    const float* __restrict__ bn_mean,
    const float* __restrict__ bn_var,
    const int*   __restrict__ num_voxels, // [4096]
    const int*   __restrict__ coors,      // [4096,4]
    float*       __restrict__ out)        // [4096,64]
{
    __shared__ __align__(16) float s_feat[TPTS + 4][12];
    // 12.8 KB buffer: phase 3 = candidate lists (u32[4*TPTS][8]),
    //                 phase 2/4 = a' in fp16 (__half2[TPTS][32])
    __shared__ __align__(16) unsigned s_ab[TPTS * 32];
    __shared__ __align__(16) float s_wta[4 * 64];
    __shared__ __align__(16) float s_wtb[4 * 64];
    __shared__ __align__(16) float s_ca[64];
    __shared__ __align__(16) float s_cb[64];
    __shared__ __align__(8)  unsigned char s_idx[TPTS][KNN];
    __shared__ __align__(16) float s_scr[512];
    __shared__ float s_red[16];
    __shared__ float s_mean[3];

    const int tid  = threadIdx.x;
    const int warp = tid >> 5;
    const int lane = tid & 31;
    const int vox  = blockIdx.x;
    int nv = num_voxels[vox];
    if (nv < 1) nv = 1;
    if (nv > TPTS) nv = TPTS;

    const float cx = (float)coors[vox * 4 + 3] * 0.2f + 0.1f;
    const float cy = (float)coors[vox * 4 + 2] * 0.2f + (-39.9f);

    // ---- phase 1a: load + mean over first 3 channels ----
    float4 fv = make_float4(0.f, 0.f, 0.f, 0.f);
    if (tid < TPTS)
        fv = reinterpret_cast<const float4*>(features)[vox * TPTS + tid];
    float sx = (tid < TPTS) ? fv.x : 0.f;
    float sy = (tid < TPTS) ? fv.y : 0.f;
    float sz = (tid < TPTS) ? fv.z : 0.f;
#pragma unroll
    for (int o = 16; o > 0; o >>= 1) {
        sx += __shfl_down_sync(0xffffffffu, sx, o);
        sy += __shfl_down_sync(0xffffffffu, sy, o);
        sz += __shfl_down_sync(0xffffffffu, sz, o);
    }
    if (lane == 0) {
        s_red[warp] = sx; s_red[4 + warp] = sy; s_red[8 + warp] = sz;
    }
    __syncthreads();
    if (tid == 0) {
        float fnv = (float)nv;
        s_mean[0] = (s_red[0] + s_red[1] + s_red[2] + s_red[3]) / fnv;
        s_mean[1] = (s_red[4] + s_red[5] + s_red[6] + s_red[7]) / fnv;
        s_mean[2] = (s_red[8] + s_red[9] + s_red[10] + s_red[11]) / fnv;
    }
    __syncthreads();

    const float mx = s_mean[0], my = s_mean[1], mz = s_mean[2];

    // ---- phase 1b: build rows; masked (t>=nv) and pad rows get key -inf ----
    if (tid < TPTS + 4) {
        float* row = s_feat[tid];
        if (tid < nv) {
            float x = fv.x, y = fv.y, z = fv.z, r = fv.w;
            float f[9];
            f[0] = x;  f[1] = y;  f[2] = z;  f[3] = r;
            f[4] = x - mx;  f[5] = y - my;  f[6] = z - mz;
            f[7] = x - cx;  f[8] = y - cy;
            float xx9 = 0.f;
#pragma unroll
            for (int c = 0; c < 9; c++) xx9 = fmaf(f[c], f[c], xx9);
            float wxx = 3.f * x * x + 3.f * y * y + 2.f * z * z + r * r;
            row[0] = x;       row[1] = y;       row[2] = z;       row[3] = r;
            row[4] = 3.f * x; row[5] = 3.f * y; row[6] = 2.f * z; row[7] = r;
            row[8] = -0.5f * wxx;
            row[9] = -0.5f * xx9;
            row[10] = 0.f; row[11] = 0.f;
        } else {
#pragma unroll
            for (int c = 0; c < 12; c++) row[c] = 0.f;
            row[8] = -__int_as_float(0x7F800000);   // -inf key, never kept
        }
    }

    // ---- phase 1c: fold BN + m/c constants into 4-dim weights ----
    if (tid < 64) {
        const int o = tid;
        float scale = bn_gamma[o] * rsqrtf(bn_var[o] + 1e-3f);
        float w1[9], wd[9];
#pragma unroll
        for (int c = 0; c < 9; c++) {
            float a = conv_w[o * 18 + c] * scale;
            float b = conv_w[o * 18 + 9 + c] * scale;
            w1[c] = a;
            wd[c] = b - a;
        }
        s_wta[0 * 64 + o] = w1[0] + w1[4] + w1[7];
        s_wta[1 * 64 + o] = w1[1] + w1[5] + w1[8];
        s_wta[2 * 64 + o] = w1[2] + w1[6];
        s_wta[3 * 64 + o] = w1[3];
        s_ca[o] = -(mx * w1[4] + my * w1[5] + mz * w1[6] + cx * w1[7] + cy * w1[8]);
        s_wtb[0 * 64 + o] = wd[0] + wd[4] + wd[7];
        s_wtb[1 * 64 + o] = wd[1] + wd[5] + wd[8];
        s_wtb[2 * 64 + o] = wd[2] + wd[6];
        s_wtb[3 * 64 + o] = wd[3];
        s_cb[o] = -(mx * wd[4] + my * wd[5] + mz * wd[6] + cx * wd[7] + cy * wd[8])
                  + bn_beta[o] - bn_mean[o] * scale;
    }
    __syncthreads();

    // ---- phase 3: warp w owns 4-aligned j-range; lanes stride t (broadcast j) ----
    unsigned* cand = s_ab;  // [4*nv][8]
    const int b0 = 4 * ((warp * nv) >> 4);
    const int b1 = (warp == 3) ? 4 * ((nv + 3) >> 2) : 4 * (((warp + 1) * nv) >> 4);

    for (int t = lane; t < nv; t += 32) {
        const float* trow = s_feat[t];
        const unsigned long long pa01 = pack2(trow[0], trow[1]);
        const unsigned long long pa23 = pack2(trow[2], trow[3]);
        const float xt_h = trow[8];

        unsigned v[KNN];
#pragma unroll
        for (int k = 0; k < KNN; k++) v[k] = 0u;

        for (int j = b0; j < b1; j += 4) {
            unsigned d[4];
#pragma unroll
            for (int u = 0; u < 4; u++) {
                const float* row = s_feat[j + u];
                const ulonglong2 jb = *reinterpret_cast<const ulonglong2*>(row + 4);
                const float cj = row[8];
                unsigned long long acc = fma_f32x2(pa01, jb.x, 0ull);
                acc = fma_f32x2(pa23, jb.y, acc);
                float lo, hi; unpack2(lo, hi, acc);
                float key = (lo + hi) + (cj + xt_h);
                d[u] = packkey(key, j + u);
            }
            cswap(d[0], d[1]); cswap(d[2], d[3]);
            cswap(d[0], d[2]); cswap(d[1], d[3]); cswap(d[1], d[2]);
            v[4] = v[4] > d[3] ? v[4] : d[3];
            v[5] = v[5] > d[2] ? v[5] : d[2];
            v[6] = v[6] > d[1] ? v[6] : d[1];
            v[7] = v[7] > d[0] ? v[7] : d[0];
            bitonic8(v);
        }
#pragma unroll
        for (int k = 0; k < KNN; k++) cand[(warp * nv + t) * KNN + k] = v[k];
    }
    __syncthreads();

    // ---- merge 4 warp-lists, fill masked analytically ----
    if (tid < nv) {
        const int t = tid;
        const int nv2 = 2 * nv, nv3 = 3 * nv;
        unsigned v[KNN], w[KNN];
#pragma unroll
        for (int k = 0; k < KNN; k++) v[k] = cand[t * KNN + k];
#pragma unroll
        for (int k = 0; k < KNN; k++) w[k] = cand[(nv + t) * KNN + k];
        merge8(v, w);
#pragma unroll
        for (int k = 0; k < KNN; k++) w[k] = cand[(nv2 + t) * KNN + k];
        merge8(v, w);
#pragma unroll
        for (int k = 0; k < KNN; k++) w[k] = cand[(nv3 + t) * KNN + k];
        merge8(v, w);
        const float mkey = s_feat[t][9];
        const unsigned mbase = ordf(mkey) & 0xFFFFFF80u;
        for (int jm = nv; jm < TPTS; jm++) {
            unsigned p = mbase | (unsigned)(127 - jm);
            if (!(p > v[KNN - 1])) break;
            ins8p(v, p);
        }
#pragma unroll
        for (int k = 0; k < KNN; k++)
            s_idx[t][k] = (unsigned char)(127u - (v[k] & 0x7Fu));
    }
    __syncthreads();

    // ---- phase 2: a'[t] = mask*(ca + p_t . wta) -> fp16x2 (overwrites cand) ----
    __half2* a16 = reinterpret_cast<__half2*>(s_ab);   // [TPTS][32] half2
    for (int p = tid; p < 50 * 16; p += 128) {
        int t  = p >> 4;
        int t2 = t + 50;
        int o4 = p & 15;
        float m1 = (t  < nv) ? 1.f : 0.f;
        float m2 = (t2 < nv) ? 1.f : 0.f;
        const float4 A1 = *reinterpret_cast<const float4*>(s_feat[t]);
        const float4 A2 = *reinterpret_cast<const float4*>(s_feat[t2]);
        float fs1[4] = {A1.x, A1.y, A1.z, A1.w};
        float fs2[4] = {A2.x, A2.y, A2.z, A2.w};
        float4 c4 = *reinterpret_cast<const float4*>(&s_ca[o4 * 4]);
        float4 acc1 = c4, acc2 = c4;
#pragma unroll
        for (int c = 0; c < 4; c++) {
            float4 wv = *reinterpret_cast<const float4*>(&s_wta[c * 64 + o4 * 4]);
            acc1.x = fmaf(fs1[c], wv.x, acc1.x);  acc2.x = fmaf(fs2[c], wv.x, acc2.x);
            acc1.y = fmaf(fs1[c], wv.y, acc1.y);  acc2.y = fmaf(fs2[c], wv.y, acc2.y);
            acc1.z = fmaf(fs1[c], wv.z, acc1.z);  acc2.z = fmaf(fs2[c], wv.z, acc2.z);
            acc1.w = fmaf(fs1[c], wv.w, acc1.w);  acc2.w = fmaf(fs2[c], wv.w, acc2.w);
        }
        acc1.x *= m1; acc1.y *= m1; acc1.z *= m1; acc1.w *= m1;
        acc2.x *= m2; acc2.y *= m2; acc2.z *= m2; acc2.w *= m2;
        a16[t  * 32 + o4 * 2]     = __floats2half2_rn(acc1.x, acc1.y);
        a16[t  * 32 + o4 * 2 + 1] = __floats2half2_rn(acc1.z, acc1.w);
        a16[t2 * 32 + o4 * 2]     = __floats2half2_rn(acc2.x, acc2.y);
        a16[t2 * 32 + o4 * 2 + 1] = __floats2half2_rn(acc2.z, acc2.w);
    }
    __syncthreads();

    // ---- phase 4: fused LDS.64 fp16 gathers + PRMT idx extraction ----
    {
        const int o4    = tid & 15;
        const int slice = tid >> 4;
        const uint2* a64 = reinterpret_cast<const uint2*>(s_ab);  // [TPTS][16] 8B units
        const __half2 hneg = __float2half2_rn(-60000.f);
        float4 rmax = make_float4(0.f, 0.f, 0.f, 0.f);
        for (int t = slice; t < nv; t += 16) {
            int t2 = t + 8;
            int t2c = (t2 < nv) ? t2 : t;
            // all 8 neighbor indices per t in one LDS.64
            const uint2 ia = *reinterpret_cast<const uint2*>(s_idx[t]);
            const uint2 ib = *reinterpret_cast<const uint2*>(s_idx[t2c]);
            __half2 ma0 = hneg, ma1 = hneg, mb0 = hneg, mb1 = hneg;
#pragma unroll
            for (int k = 0; k < KNN; k++) {
                unsigned wa = (k < 4) ? ia.x : ia.y;
                unsigned wb = (k < 4) ? ib.x : ib.y;
                int ja = (int)__byte_perm(wa, 0u, 0x4440u | (k & 3));
                int jb = (int)__byte_perm(wb, 0u, 0x4440u | (k & 3));
                uint2 pa = a64[ja * 16 + o4];
                uint2 pb = a64[jb * 16 + o4];
                ma0 = __hmax2(ma0, *reinterpret_cast<__half2*>(&pa.x));
                ma1 = __hmax2(ma1, *reinterpret_cast<__half2*>(&pa.y));
                mb0 = __hmax2(mb0, *reinterpret_cast<__half2*>(&pb.x));
                mb1 = __hmax2(mb1, *reinterpret_cast<__half2*>(&pb.y));
            }
            float2 fa0 = __half22float2(ma0), fa1 = __half22float2(ma1);
            float2 fb0 = __half22float2(mb0), fb1 = __half22float2(mb1);
            float4 m4a = make_float4(fa0.x, fa0.y, fa1.x, fa1.y);
            float4 m4b = make_float4(fb0.x, fb0.y, fb1.x, fb1.y);

            const float4 A1 = *reinterpret_cast<const float4*>(s_feat[t]);
            const float4 A2 = *reinterpret_cast<const float4*>(s_feat[t2c]);
            float fs1[4] = {A1.x, A1.y, A1.z, A1.w};
            float fs2[4] = {A2.x, A2.y, A2.z, A2.w};
            float4 cb4 = *reinterpret_cast<const float4*>(&s_cb[o4 * 4]);
            float4 b1 = cb4, b2 = cb4;
#pragma unroll
            for (int c = 0; c < 4; c++) {
                float4 wv = *reinterpret_cast<const float4*>(&s_wtb[c * 64 + o4 * 4]);
                b1.x = fmaf(fs1[c], wv.x, b1.x);  b2.x = fmaf(fs2[c], wv.x, b2.x);
                b1.y = fmaf(fs1[c], wv.y, b1.y);  b2.y = fmaf(fs2[c], wv.y, b2.y);
                b1.z = fmaf(fs1[c], wv.z, b1.z);  b2.z = fmaf(fs2[c], wv.z, b2.z);
                b1.w = fmaf(fs1[c], wv.w, b1.w);  b2.w = fmaf(fs2[c], wv.w, b2.w);
            }
            float4 h1 = lrelu4(m4a, b1);
            float4 h2 = lrelu4(m4b, b2);
            rmax.x = fmaxf(rmax.x, fmaxf(h1.x, h2.x));
            rmax.y = fmaxf(rmax.y, fmaxf(h1.y, h2.y));
            rmax.z = fmaxf(rmax.z, fmaxf(h1.z, h2.z));
            rmax.w = fmaxf(rmax.w, fmaxf(h1.w, h2.w));
        }
        reinterpret_cast<float4*>(s_scr)[slice * 16 + o4] = rmax;
    }
    __syncthreads();

    if (tid < 64) {
        float r = s_scr[tid];
#pragma unroll
        for (int s = 1; s < 8; s++) r = fmaxf(r, s_scr[s * 64 + tid]);
        out[vox * 64 + tid] = r;
    }
}

extern "C" void kernel_launch(void* const* d_in, const int* in_sizes, int n_in,
                              void* d_out, int out_size) {
    const float* features   = (const float*)d_in[0];
    const float* conv_w     = (const float*)d_in[1];
    const float* bn_gamma   = (const float*)d_in[2];
    const float* bn_beta    = (const float*)d_in[3];
    const float* bn_mean    = (const float*)d_in[4];
    const float* bn_var     = (const float*)d_in[5];
    const int*   num_voxels = (const int*)d_in[6];
    const int*   coors      = (const int*)d_in[7];
    float*       out        = (float*)d_out;

    gcn_kernel<<<VOX, 128>>>(features, conv_w, bn_gamma, bn_beta, bn_mean, bn_var,
                             num_voxels, coors, out);
}

// round 13
// speedup vs baseline: 1.5371x; 1.0579x over previous
#include <cuda_runtime.h>
#include <cuda_fp16.h>
#include <math.h>

#define VOX   4096
#define TPTS  100
#define KNN   8

// pack: top 25 bits of order-flipped key | (127 - j).
// VALID ONLY because keys here are <= 0 (negdist/2): for sign-bit-set floats
// the order-preserving map ordf(u) == ~u. The lone near-zero (possibly +eps)
// self-key maps to the top of the order under ~u, which is where it belongs;
// only top-8 SET membership matters (we max over the 8).
__device__ __forceinline__ unsigned packkey(float key, int jcode) {
    return (~__float_as_uint(key) & 0xFFFFFF80u) | (unsigned)jcode;
}

__device__ __forceinline__ void cswap(unsigned& a, unsigned& b) {
    unsigned mx = a > b ? a : b;
    unsigned mn = a > b ? b : a;
    a = mx; b = mn;
}

// sort a bitonic 8-sequence into descending order (12 comparators)
__device__ __forceinline__ void bitonic8(unsigned v[KNN]) {
    cswap(v[0], v[4]); cswap(v[1], v[5]); cswap(v[2], v[6]); cswap(v[3], v[7]);
    cswap(v[0], v[2]); cswap(v[1], v[3]); cswap(v[4], v[6]); cswap(v[5], v[7]);
    cswap(v[0], v[1]); cswap(v[2], v[3]); cswap(v[4], v[5]); cswap(v[6], v[7]);
}

// merge sorted-desc w[8] into sorted-desc v[8], keeping top-8
__device__ __forceinline__ void merge8(unsigned v[KNN], const unsigned w[KNN]) {
#pragma unroll
    for (int i = 0; i < KNN; i++) {
        unsigned b = w[KNN - 1 - i];
        v[i] = v[i] > b ? v[i] : b;
    }
    bitonic8(v);
}

// single insert (short masked-fill loop only)
__device__ __forceinline__ void ins8p(unsigned v[KNN], unsigned d) {
#pragma unroll
    for (int s = 0; s < KNN; s++) {
        unsigned vs = v[s];
        v[s] = vs > d ? vs : d;
        d    = vs > d ? d : vs;
    }
}

__device__ __forceinline__ unsigned long long fma_f32x2(
    unsigned long long a, unsigned long long b, unsigned long long c) {
    unsigned long long d;
    asm("fma.rn.f32x2 %0, %1, %2, %3;" : "=l"(d) : "l"(a), "l"(b), "l"(c));
    return d;
}
__device__ __forceinline__ unsigned long long mul_f32x2(
    unsigned long long a, unsigned long long b) {
    unsigned long long d;
    asm("mul.rn.f32x2 %0, %1, %2;" : "=l"(d) : "l"(a), "l"(b));
    return d;
}
__device__ __forceinline__ unsigned long long pack2(float lo, float hi) {
    unsigned long long r;
    asm("mov.b64 %0, {%1, %2};" : "=l"(r) : "f"(lo), "f"(hi));
    return r;
}
__device__ __forceinline__ void unpack2(float& lo, float& hi, unsigned long long v) {
    asm("mov.b64 {%0, %1}, %2;" : "=f"(lo), "=f"(hi) : "l"(v));
}

// s_feat row (12 floats): [0..3]=(x,y,z,r)  [4..7]=(3x,3y,2z,r)
//                         [8]=-wxx/2 (-inf on masked/pad rows)  [9]=-xx9/2
__global__ __launch_bounds__(128, 9) void gcn_kernel(
    const float* __restrict__ features,   // [4096,100,4]
    const float* __restrict__ conv_w,     // [64,18]
    const float* __restrict__ bn_gamma,
    const float* __restrict__ bn_beta,
    const float* __restrict__ bn_mean,
    const float* __restrict__ bn_var,
    const int*   __restrict__ num_voxels, // [4096]
    const int*   __restrict__ coors,      // [4096,4]
    float*       __restrict__ out)        // [4096,64]
{
    __shared__ __align__(16) float s_feat[TPTS + 4][12];
    // 12.8 KB buffer: phase 3 = candidate lists (u32[4*TPTS][8]),
    //                 phase 2/4 = a' in fp16 (__half2[TPTS][32])
    __shared__ __align__(16) unsigned s_ab[TPTS * 32];
    __shared__ __align__(16) float s_wta[4 * 64];
    __shared__ __align__(16) float s_wtb[4 * 64];
    __shared__ __align__(16) float s_ca[64];
    __shared__ __align__(16) float s_cb[64];
    __shared__ __align__(8)  unsigned char s_idx[TPTS][KNN];
    __shared__ __align__(16) float s_scr[512];
    __shared__ float s_red[16];
    __shared__ float s_mean[3];

    const int tid  = threadIdx.x;
    const int warp = tid >> 5;
    const int lane = tid & 31;
    const int vox  = blockIdx.x;
    int nv = num_voxels[vox];
    if (nv < 1) nv = 1;
    if (nv > TPTS) nv = TPTS;

    const float cx = (float)coors[vox * 4 + 3] * 0.2f + 0.1f;
    const float cy = (float)coors[vox * 4 + 2] * 0.2f + (-39.9f);

    // ---- phase 1a: load + mean over first 3 channels ----
    float4 fv = make_float4(0.f, 0.f, 0.f, 0.f);
    if (tid < TPTS)
        fv = reinterpret_cast<const float4*>(features)[vox * TPTS + tid];
    float sx = (tid < TPTS) ? fv.x : 0.f;
    float sy = (tid < TPTS) ? fv.y : 0.f;
    float sz = (tid < TPTS) ? fv.z : 0.f;
#pragma unroll
    for (int o = 16; o > 0; o >>= 1) {
        sx += __shfl_down_sync(0xffffffffu, sx, o);
        sy += __shfl_down_sync(0xffffffffu, sy, o);
        sz += __shfl_down_sync(0xffffffffu, sz, o);
    }
    if (lane == 0) {
        s_red[warp] = sx; s_red[4 + warp] = sy; s_red[8 + warp] = sz;
    }
    __syncthreads();
    if (tid == 0) {
        float fnv = (float)nv;
        s_mean[0] = (s_red[0] + s_red[1] + s_red[2] + s_red[3]) / fnv;
        s_mean[1] = (s_red[4] + s_red[5] + s_red[6] + s_red[7]) / fnv;
        s_mean[2] = (s_red[8] + s_red[9] + s_red[10] + s_red[11]) / fnv;
    }
    __syncthreads();

    const float mx = s_mean[0], my = s_mean[1], mz = s_mean[2];

    // ---- phase 1b: build rows; masked (t>=nv) and pad rows get key -inf ----
    if (tid < TPTS + 4) {
        float* row = s_feat[tid];
        if (tid < nv) {
            float x = fv.x, y = fv.y, z = fv.z, r = fv.w;
            float f[9];
            f[0] = x;  f[1] = y;  f[2] = z;  f[3] = r;
            f[4] = x - mx;  f[5] = y - my;  f[6] = z - mz;
            f[7] = x - cx;  f[8] = y - cy;
            float xx9 = 0.f;
#pragma unroll
            for (int c = 0; c < 9; c++) xx9 = fmaf(f[c], f[c], xx9);
            float wxx = 3.f * x * x + 3.f * y * y + 2.f * z * z + r * r;
            row[0] = x;       row[1] = y;       row[2] = z;       row[3] = r;
            row[4] = 3.f * x; row[5] = 3.f * y; row[6] = 2.f * z; row[7] = r;
            row[8] = -0.5f * wxx;
            row[9] = -0.5f * xx9;
            row[10] = 0.f; row[11] = 0.f;
        } else {
#pragma unroll
            for (int c = 0; c < 12; c++) row[c] = 0.f;
            row[8] = -__int_as_float(0x7F800000);   // -inf key, never kept
        }
    }

    // ---- phase 1c: fold BN + m/c constants into 4-dim weights ----
    if (tid < 64) {
        const int o = tid;
        float scale = bn_gamma[o] * rsqrtf(bn_var[o] + 1e-3f);
        float w1[9], wd[9];
#pragma unroll
        for (int c = 0; c < 9; c++) {
            float a = conv_w[o * 18 + c] * scale;
            float b = conv_w[o * 18 + 9 + c] * scale;
            w1[c] = a;
            wd[c] = b - a;
        }
        s_wta[0 * 64 + o] = w1[0] + w1[4] + w1[7];
        s_wta[1 * 64 + o] = w1[1] + w1[5] + w1[8];
        s_wta[2 * 64 + o] = w1[2] + w1[6];
        s_wta[3 * 64 + o] = w1[3];
        s_ca[o] = -(mx * w1[4] + my * w1[5] + mz * w1[6] + cx * w1[7] + cy * w1[8]);
        s_wtb[0 * 64 + o] = wd[0] + wd[4] + wd[7];
        s_wtb[1 * 64 + o] = wd[1] + wd[5] + wd[8];
        s_wtb[2 * 64 + o] = wd[2] + wd[6];
        s_wtb[3 * 64 + o] = wd[3];
        s_cb[o] = -(mx * wd[4] + my * wd[5] + mz * wd[6] + cx * wd[7] + cy * wd[8])
                  + bn_beta[o] - bn_mean[o] * scale;
    }
    __syncthreads();

    // ---- phase 3: warp w owns 4-aligned j-range; lanes stride t (broadcast j) ----
    unsigned* cand = s_ab;  // [4*nv][8]
    const int b0 = 4 * ((warp * nv) >> 4);
    const int b1 = (warp == 3) ? 4 * ((nv + 3) >> 2) : 4 * (((warp + 1) * nv) >> 4);

    for (int t = lane; t < nv; t += 32) {
        const float* trow = s_feat[t];
        const unsigned long long pa01 = pack2(trow[0], trow[1]);
        const unsigned long long pa23 = pack2(trow[2], trow[3]);
        const unsigned long long init = pack2(trow[8], 0.f);   // xt_h folded in

        unsigned v[KNN];
#pragma unroll
        for (int k = 0; k < KNN; k++) v[k] = 0u;

        for (int j = b0; j < b1; j += 4) {
            unsigned d[4];
            const int jj = 127 - j;
#pragma unroll
            for (int u = 0; u < 4; u++) {
                const float* row = s_feat[j + u];
                const ulonglong2 jv = *reinterpret_cast<const ulonglong2*>(row + 4);
                const float cj = row[8];
                unsigned long long acc = fma_f32x2(pa01, jv.x, init);
                acc = fma_f32x2(pa23, jv.y, acc);
                float lo, hi; unpack2(lo, hi, acc);
                float key = (lo + hi) + cj;
                d[u] = packkey(key, jj - u);
            }
            cswap(d[0], d[1]); cswap(d[2], d[3]);
            cswap(d[0], d[2]); cswap(d[1], d[3]); cswap(d[1], d[2]);
            v[4] = v[4] > d[3] ? v[4] : d[3];
            v[5] = v[5] > d[2] ? v[5] : d[2];
            v[6] = v[6] > d[1] ? v[6] : d[1];
            v[7] = v[7] > d[0] ? v[7] : d[0];
            bitonic8(v);
        }
#pragma unroll
        for (int k = 0; k < KNN; k++) cand[(warp * nv + t) * KNN + k] = v[k];
    }
    __syncthreads();

    // ---- merge 4 warp-lists, fill masked analytically (true key -xx9_t/2) ----
    if (tid < nv) {
        const int t = tid;
        const int nv2 = 2 * nv, nv3 = 3 * nv;
        unsigned v[KNN], w[KNN];
#pragma unroll
        for (int k = 0; k < KNN; k++) v[k] = cand[t * KNN + k];
#pragma unroll
        for (int k = 0; k < KNN; k++) w[k] = cand[(nv + t) * KNN + k];
        merge8(v, w);
#pragma unroll
        for (int k = 0; k < KNN; k++) w[k] = cand[(nv2 + t) * KNN + k];
        merge8(v, w);
#pragma unroll
        for (int k = 0; k < KNN; k++) w[k] = cand[(nv3 + t) * KNN + k];
        merge8(v, w);
        const float mkey = s_feat[t][9];                 // <= 0
        const unsigned mbase = ~__float_as_uint(mkey) & 0xFFFFFF80u;
        for (int jm = nv; jm < TPTS; jm++) {
            unsigned p = mbase | (unsigned)(127 - jm);
            if (!(p > v[KNN - 1])) break;
            ins8p(v, p);
        }
#pragma unroll
        for (int k = 0; k < KNN; k++)
            s_idx[t][k] = (unsigned char)(127u - (v[k] & 0x7Fu));
    }
    __syncthreads();

    // ---- phase 2: a'[t] = mask*(ca + p_t . wta) via f32x2 -> fp16x2 ----
    __half2* a16 = reinterpret_cast<__half2*>(s_ab);   // [TPTS][32] half2
    {
        const ulonglong2* wta2 = reinterpret_cast<const ulonglong2*>(s_wta);
        for (int p = tid; p < 50 * 16; p += 128) {
            int t  = p >> 4;
            int t2 = t + 50;
            int o4 = p & 15;
            float m1 = (t  < nv) ? 1.f : 0.f;
            float m2 = (t2 < nv) ? 1.f : 0.f;
            const float4 A1 = *reinterpret_cast<const float4*>(s_feat[t]);
            const float4 A2 = *reinterpret_cast<const float4*>(s_feat[t2]);
            float fs1[4] = {A1.x, A1.y, A1.z, A1.w};
            float fs2[4] = {A2.x, A2.y, A2.z, A2.w};
            const float4 c4 = *reinterpret_cast<const float4*>(&s_ca[o4 * 4]);
            unsigned long long acc1a = pack2(c4.x, c4.y), acc1b = pack2(c4.z, c4.w);
            unsigned long long acc2a = acc1a, acc2b = acc1b;
#pragma unroll
            for (int c = 0; c < 4; c++) {
                ulonglong2 wv = wta2[c * 16 + o4];
                unsigned long long f1 = pack2(fs1[c], fs1[c]);
                unsigned long long f2 = pack2(fs2[c], fs2[c]);
                acc1a = fma_f32x2(f1, wv.x, acc1a);
                acc1b = fma_f32x2(f1, wv.y, acc1b);
                acc2a = fma_f32x2(f2, wv.x, acc2a);
                acc2b = fma_f32x2(f2, wv.y, acc2b);
            }
            unsigned long long m1p = pack2(m1, m1), m2p = pack2(m2, m2);
            acc1a = mul_f32x2(acc1a, m1p);  acc1b = mul_f32x2(acc1b, m1p);
            acc2a = mul_f32x2(acc2a, m2p);  acc2b = mul_f32x2(acc2b, m2p);
            float e0, e1;
            unpack2(e0, e1, acc1a); a16[t  * 32 + o4 * 2]     = __floats2half2_rn(e0, e1);
            unpack2(e0, e1, acc1b); a16[t  * 32 + o4 * 2 + 1] = __floats2half2_rn(e0, e1);
            unpack2(e0, e1, acc2a); a16[t2 * 32 + o4 * 2]     = __floats2half2_rn(e0, e1);
            unpack2(e0, e1, acc2b); a16[t2 * 32 + o4 * 2 + 1] = __floats2half2_rn(e0, e1);
        }
    }
    __syncthreads();

    // ---- phase 4: fused LDS.64 gathers + PRMT idx; b' via f32x2; NO lrelu
    //      (monotone: max(0, max_t lrelu(h)) == max(0, max_t h)) ----
    {
        const int o4    = tid & 15;
        const int slice = tid >> 4;
        const uint2* a64 = reinterpret_cast<const uint2*>(s_ab);  // [TPTS][16] 8B
        const ulonglong2* wtb2 = reinterpret_cast<const ulonglong2*>(s_wtb);
        const __half2 hneg = __float2half2_rn(-60000.f);
        float4 rmax = make_float4(0.f, 0.f, 0.f, 0.f);
        for (int t = slice; t < nv; t += 16) {
            int t2 = t + 8;
            int t2c = (t2 < nv) ? t2 : t;
            const uint2 ia = *reinterpret_cast<const uint2*>(s_idx[t]);
            const uint2 ib = *reinterpret_cast<const uint2*>(s_idx[t2c]);
            __half2 ma0 = hneg, ma1 = hneg, mb0 = hneg, mb1 = hneg;
#pragma unroll
            for (int k = 0; k < KNN; k++) {
                unsigned wa = (k < 4) ? ia.x : ia.y;
                unsigned wb = (k < 4) ? ib.x : ib.y;
                int ja = (int)__byte_perm(wa, 0u, 0x4440u | (k & 3));
                int jb = (int)__byte_perm(wb, 0u, 0x4440u | (k & 3));
                uint2 pa = a64[ja * 16 + o4];
                uint2 pb = a64[jb * 16 + o4];
                ma0 = __hmax2(ma0, *reinterpret_cast<__half2*>(&pa.x));
                ma1 = __hmax2(ma1, *reinterpret_cast<__half2*>(&pa.y));
                mb0 = __hmax2(mb0, *reinterpret_cast<__half2*>(&pb.x));
                mb1 = __hmax2(mb1, *reinterpret_cast<__half2*>(&pb.y));
            }
            const float4 A1 = *reinterpret_cast<const float4*>(s_feat[t]);
            const float4 A2 = *reinterpret_cast<const float4*>(s_feat[t2c]);
            float fs1[4] = {A1.x, A1.y, A1.z, A1.w};
            float fs2[4] = {A2.x, A2.y, A2.z, A2.w};
            const float4 cb4 = *reinterpret_cast<const float4*>(&s_cb[o4 * 4]);
            unsigned long long b1a = pack2(cb4.x, cb4.y), b1b = pack2(cb4.z, cb4.w);
            unsigned long long b2a = b1a, b2b = b1b;
#pragma unroll
            for (int c = 0; c < 4; c++) {
                ulonglong2 wv = wtb2[c * 16 + o4];
                unsigned long long f1 = pack2(fs1[c], fs1[c]);
                unsigned long long f2 = pack2(fs2[c], fs2[c]);
                b1a = fma_f32x2(f1, wv.x, b1a);
                b1b = fma_f32x2(f1, wv.y, b1b);
                b2a = fma_f32x2(f2, wv.x, b2a);
                b2b = fma_f32x2(f2, wv.y, b2b);
            }
            float b1x, b1y, b1z, b1w, b2x, b2y, b2z, b2w;
            unpack2(b1x, b1y, b1a);  unpack2(b1z, b1w, b1b);
            unpack2(b2x, b2y, b2a);  unpack2(b2z, b2w, b2b);
            float2 fa0 = __half22float2(ma0), fa1 = __half22float2(ma1);
            float2 fb0 = __half22float2(mb0), fb1 = __half22float2(mb1);
            rmax.x = fmaxf(rmax.x, fmaxf(fa0.x + b1x, fb0.x + b2x));
            rmax.y = fmaxf(rmax.y, fmaxf(fa0.y + b1y, fb0.y + b2y));
            rmax.z = fmaxf(rmax.z, fmaxf(fa1.x + b1z, fb1.x + b2z));
            rmax.w = fmaxf(rmax.w, fmaxf(fa1.y + b1w, fb1.y + b2w));
        }
        reinterpret_cast<float4*>(s_scr)[slice * 16 + o4] = rmax;
    }
    __syncthreads();

    if (tid < 64) {
        float r = s_scr[tid];
#pragma unroll
        for (int s = 1; s < 8; s++) r = fmaxf(r, s_scr[s * 64 + tid]);
        out[vox * 64 + tid] = r;
    }
}

extern "C" void kernel_launch(void* const* d_in, const int* in_sizes, int n_in,
                              void* d_out, int out_size) {
    const float* features   = (const float*)d_in[0];
    const float* conv_w     = (const float*)d_in[1];
    const float* bn_gamma   = (const float*)d_in[2];
    const float* bn_beta    = (const float*)d_in[3];
    const float* bn_mean    = (const float*)d_in[4];
    const float* bn_var     = (const float*)d_in[5];
    const int*   num_voxels = (const int*)d_in[6];
    const int*   coors      = (const int*)d_in[7];
    float*       out        = (float*)d_out;

    gcn_kernel<<<VOX, 128>>>(features, conv_w, bn_gamma, bn_beta, bn_mean, bn_var,
                             num_voxels, coors, out);
}

// round 14
// speedup vs baseline: 1.5382x; 1.0007x over previous
#include <cuda_runtime.h>
#include <cuda_fp16.h>
#include <math.h>

#define VOX   4096
#define TPTS  100
#define KNN   8

// pack: top 25 bits of order-flipped key | (127 - j).
// VALID ONLY because keys here are <= 0 (negdist/2): for sign-bit-set floats
// the order-preserving map ordf(u) == ~u. The lone near-zero (possibly +eps)
// self-key maps to the top of the order under ~u, which is where it belongs;
// only top-8 SET membership matters (we max over the 8).
__device__ __forceinline__ unsigned packkey(float key, int jcode) {
    return (~__float_as_uint(key) & 0xFFFFFF80u) | (unsigned)jcode;
}

__device__ __forceinline__ void cswap(unsigned& a, unsigned& b) {
    unsigned mx = a > b ? a : b;
    unsigned mn = a > b ? b : a;
    a = mx; b = mn;
}

// sort a bitonic 8-sequence into descending order (12 comparators)
__device__ __forceinline__ void bitonic8(unsigned v[KNN]) {
    cswap(v[0], v[4]); cswap(v[1], v[5]); cswap(v[2], v[6]); cswap(v[3], v[7]);
    cswap(v[0], v[2]); cswap(v[1], v[3]); cswap(v[4], v[6]); cswap(v[5], v[7]);
    cswap(v[0], v[1]); cswap(v[2], v[3]); cswap(v[4], v[5]); cswap(v[6], v[7]);
}

// merge sorted-desc w[8] into sorted-desc v[8], keeping top-8
__device__ __forceinline__ void merge8(unsigned v[KNN], const unsigned w[KNN]) {
#pragma unroll
    for (int i = 0; i < KNN; i++) {
        unsigned b = w[KNN - 1 - i];
        v[i] = v[i] > b ? v[i] : b;
    }
    bitonic8(v);
}

// single insert (short masked-fill loop only)
__device__ __forceinline__ void ins8p(unsigned v[KNN], unsigned d) {
#pragma unroll
    for (int s = 0; s < KNN; s++) {
        unsigned vs = v[s];
        v[s] = vs > d ? vs : d;
        d    = vs > d ? d : vs;
    }
}

__device__ __forceinline__ unsigned long long fma_f32x2(
    unsigned long long a, unsigned long long b, unsigned long long c) {
    unsigned long long d;
    asm("fma.rn.f32x2 %0, %1, %2, %3;" : "=l"(d) : "l"(a), "l"(b), "l"(c));
    return d;
}
__device__ __forceinline__ unsigned long long mul_f32x2(
    unsigned long long a, unsigned long long b) {
    unsigned long long d;
    asm("mul.rn.f32x2 %0, %1, %2;" : "=l"(d) : "l"(a), "l"(b));
    return d;
}
__device__ __forceinline__ unsigned long long pack2(float lo, float hi) {
    unsigned long long r;
    asm("mov.b64 %0, {%1, %2};" : "=l"(r) : "f"(lo), "f"(hi));
    return r;
}
__device__ __forceinline__ void unpack2(float& lo, float& hi, unsigned long long v) {
    asm("mov.b64 {%0, %1}, %2;" : "=f"(lo), "=f"(hi) : "l"(v));
}

// s_feat row (12 floats): [0..3]=(x,y,z,r)  [4..7]=(3x,3y,2z,r)
//                         [8]=-wxx/2 (-inf on masked/pad rows)  [9]=-xx9/2
__global__ __launch_bounds__(128, 9) void gcn_kernel(
    const float* __restrict__ features,   // [4096,100,4]
    const float* __restrict__ conv_w,     // [64,18]
    const float* __restrict__ bn_gamma,
    const float* __restrict__ bn_beta,
    const float* __restrict__ bn_mean,
    const float* __restrict__ bn_var,
    const int*   __restrict__ num_voxels, // [4096]
    const int*   __restrict__ coors,      // [4096,4]
    float*       __restrict__ out)        // [4096,64]
{
    __shared__ __align__(16) float s_feat[TPTS + 4][12];
    // 12.8 KB buffer: phase 3 = candidate lists (u32[4*TPTS][8]),
    //                 phase 2/4 = a' in fp16 (__half2[TPTS][32])
    __shared__ __align__(16) unsigned s_ab[TPTS * 32];
    __shared__ __align__(16) float s_wta[4 * 64];
    __shared__ __align__(16) float s_wtb[4 * 64];
    __shared__ __align__(16) float s_ca[64];
    __shared__ __align__(16) float s_cb[64];
    __shared__ __align__(8)  unsigned char s_idx[TPTS][KNN];
    __shared__ __align__(16) float s_scr[256];     // 4 warp-partials x 64 ch
    __shared__ float s_red[16];
    __shared__ float s_mean[3];

    const int tid  = threadIdx.x;
    const int warp = tid >> 5;
    const int lane = tid & 31;
    const int vox  = blockIdx.x;
    int nv = num_voxels[vox];
    if (nv < 1) nv = 1;
    if (nv > TPTS) nv = TPTS;

    const float cx = (float)coors[vox * 4 + 3] * 0.2f + 0.1f;
    const float cy = (float)coors[vox * 4 + 2] * 0.2f + (-39.9f);

    // ---- phase 1a: load + mean over first 3 channels ----
    float4 fv = make_float4(0.f, 0.f, 0.f, 0.f);
    if (tid < TPTS)
        fv = reinterpret_cast<const float4*>(features)[vox * TPTS + tid];
    float sx = (tid < TPTS) ? fv.x : 0.f;
    float sy = (tid < TPTS) ? fv.y : 0.f;
    float sz = (tid < TPTS) ? fv.z : 0.f;
#pragma unroll
    for (int o = 16; o > 0; o >>= 1) {
        sx += __shfl_down_sync(0xffffffffu, sx, o);
        sy += __shfl_down_sync(0xffffffffu, sy, o);
        sz += __shfl_down_sync(0xffffffffu, sz, o);
    }
    if (lane == 0) {
        s_red[warp] = sx; s_red[4 + warp] = sy; s_red[8 + warp] = sz;
    }
    __syncthreads();
    if (tid == 0) {
        float fnv = (float)nv;
        s_mean[0] = (s_red[0] + s_red[1] + s_red[2] + s_red[3]) / fnv;
        s_mean[1] = (s_red[4] + s_red[5] + s_red[6] + s_red[7]) / fnv;
        s_mean[2] = (s_red[8] + s_red[9] + s_red[10] + s_red[11]) / fnv;
    }
    __syncthreads();

    const float mx = s_mean[0], my = s_mean[1], mz = s_mean[2];

    // ---- phase 1b: build rows; masked (t>=nv) and pad rows get key -inf ----
    if (tid < TPTS + 4) {
        float* row = s_feat[tid];
        if (tid < nv) {
            float x = fv.x, y = fv.y, z = fv.z, r = fv.w;
            float f[9];
            f[0] = x;  f[1] = y;  f[2] = z;  f[3] = r;
            f[4] = x - mx;  f[5] = y - my;  f[6] = z - mz;
            f[7] = x - cx;  f[8] = y - cy;
            float xx9 = 0.f;
#pragma unroll
            for (int c = 0; c < 9; c++) xx9 = fmaf(f[c], f[c], xx9);
            float wxx = 3.f * x * x + 3.f * y * y + 2.f * z * z + r * r;
            row[0] = x;       row[1] = y;       row[2] = z;       row[3] = r;
            row[4] = 3.f * x; row[5] = 3.f * y; row[6] = 2.f * z; row[7] = r;
            row[8] = -0.5f * wxx;
            row[9] = -0.5f * xx9;
            row[10] = 0.f; row[11] = 0.f;
        } else {
#pragma unroll
            for (int c = 0; c < 12; c++) row[c] = 0.f;
            row[8] = -__int_as_float(0x7F800000);   // -inf key, never kept
        }
    }

    // ---- phase 1c: fold BN + m/c constants into 4-dim weights ----
    if (tid < 64) {
        const int o = tid;
        float scale = bn_gamma[o] * rsqrtf(bn_var[o] + 1e-3f);
        float w1[9], wd[9];
#pragma unroll
        for (int c = 0; c < 9; c++) {
            float a = conv_w[o * 18 + c] * scale;
            float b = conv_w[o * 18 + 9 + c] * scale;
            w1[c] = a;
            wd[c] = b - a;
        }
        s_wta[0 * 64 + o] = w1[0] + w1[4] + w1[7];
        s_wta[1 * 64 + o] = w1[1] + w1[5] + w1[8];
        s_wta[2 * 64 + o] = w1[2] + w1[6];
        s_wta[3 * 64 + o] = w1[3];
        s_ca[o] = -(mx * w1[4] + my * w1[5] + mz * w1[6] + cx * w1[7] + cy * w1[8]);
        s_wtb[0 * 64 + o] = wd[0] + wd[4] + wd[7];
        s_wtb[1 * 64 + o] = wd[1] + wd[5] + wd[8];
        s_wtb[2 * 64 + o] = wd[2] + wd[6];
        s_wtb[3 * 64 + o] = wd[3];
        s_cb[o] = -(mx * wd[4] + my * wd[5] + mz * wd[6] + cx * wd[7] + cy * wd[8])
                  + bn_beta[o] - bn_mean[o] * scale;
    }
    __syncthreads();

    // ---- phase 3: warp w owns 4-aligned j-range; lanes stride t (broadcast j) ----
    uint4* cand4 = reinterpret_cast<uint4*>(s_ab);  // [4*nv][2] uint4
    const int b0 = 4 * ((warp * nv) >> 4);
    const int b1 = (warp == 3) ? 4 * ((nv + 3) >> 2) : 4 * (((warp + 1) * nv) >> 4);

    for (int t = lane; t < nv; t += 32) {
        const float* trow = s_feat[t];
        const unsigned long long pa01 = pack2(trow[0], trow[1]);
        const unsigned long long pa23 = pack2(trow[2], trow[3]);
        const unsigned long long init = pack2(trow[8], 0.f);   // xt_h folded in

        unsigned v[KNN];
#pragma unroll
        for (int k = 0; k < KNN; k++) v[k] = 0u;

#pragma unroll 2
        for (int j = b0; j < b1; j += 4) {
            unsigned d[4];
            const int jj = 127 - j;
#pragma unroll
            for (int u = 0; u < 4; u++) {
                const float* row = s_feat[j + u];
                const ulonglong2 jv = *reinterpret_cast<const ulonglong2*>(row + 4);
                const float cj = row[8];
                unsigned long long acc = fma_f32x2(pa01, jv.x, init);
                acc = fma_f32x2(pa23, jv.y, acc);
                float lo, hi; unpack2(lo, hi, acc);
                float key = (lo + hi) + cj;
                d[u] = packkey(key, jj - u);
            }
            cswap(d[0], d[1]); cswap(d[2], d[3]);
            cswap(d[0], d[2]); cswap(d[1], d[3]); cswap(d[1], d[2]);
            v[4] = v[4] > d[3] ? v[4] : d[3];
            v[5] = v[5] > d[2] ? v[5] : d[2];
            v[6] = v[6] > d[1] ? v[6] : d[1];
            v[7] = v[7] > d[0] ? v[7] : d[0];
            bitonic8(v);
        }
        const int rowi = (warp * nv + t) * 2;
        cand4[rowi]     = make_uint4(v[0], v[1], v[2], v[3]);
        cand4[rowi + 1] = make_uint4(v[4], v[5], v[6], v[7]);
    }
    __syncthreads();

    // ---- merge 4 warp-lists (uint4 loads), fill masked analytically ----
    if (tid < nv) {
        const int t = tid;
        unsigned v[KNN], w[KNN];
        uint4 p0 = cand4[t * 2], p1 = cand4[t * 2 + 1];
        v[0] = p0.x; v[1] = p0.y; v[2] = p0.z; v[3] = p0.w;
        v[4] = p1.x; v[5] = p1.y; v[6] = p1.z; v[7] = p1.w;
#pragma unroll
        for (int q = 1; q < 4; q++) {
            uint4 q0 = cand4[(q * nv + t) * 2], q1 = cand4[(q * nv + t) * 2 + 1];
            w[0] = q0.x; w[1] = q0.y; w[2] = q0.z; w[3] = q0.w;
            w[4] = q1.x; w[5] = q1.y; w[6] = q1.z; w[7] = q1.w;
            merge8(v, w);
        }
        const float mkey = s_feat[t][9];                 // <= 0
        const unsigned mbase = ~__float_as_uint(mkey) & 0xFFFFFF80u;
        for (int jm = nv; jm < TPTS; jm++) {
            unsigned p = mbase | (unsigned)(127 - jm);
            if (!(p > v[KNN - 1])) break;
            ins8p(v, p);
        }
#pragma unroll
        for (int k = 0; k < KNN; k++)
            s_idx[t][k] = (unsigned char)(127u - (v[k] & 0x7Fu));
    }
    __syncthreads();

    // ---- phase 2: a'[t] = mask*(ca + p_t . wta) via f32x2 -> fp16x2 ----
    __half2* a16 = reinterpret_cast<__half2*>(s_ab);   // [TPTS][32] half2
    {
        const ulonglong2* wta2 = reinterpret_cast<const ulonglong2*>(s_wta);
        for (int p = tid; p < 50 * 16; p += 128) {
            int t  = p >> 4;
            int t2 = t + 50;
            int o4 = p & 15;
            float m1 = (t  < nv) ? 1.f : 0.f;
            float m2 = (t2 < nv) ? 1.f : 0.f;
            const float4 A1 = *reinterpret_cast<const float4*>(s_feat[t]);
            const float4 A2 = *reinterpret_cast<const float4*>(s_feat[t2]);
            float fs1[4] = {A1.x, A1.y, A1.z, A1.w};
            float fs2[4] = {A2.x, A2.y, A2.z, A2.w};
            const float4 c4 = *reinterpret_cast<const float4*>(&s_ca[o4 * 4]);
            unsigned long long acc1a = pack2(c4.x, c4.y), acc1b = pack2(c4.z, c4.w);
            unsigned long long acc2a = acc1a, acc2b = acc1b;
#pragma unroll
            for (int c = 0; c < 4; c++) {
                ulonglong2 wv = wta2[c * 16 + o4];
                unsigned long long f1 = pack2(fs1[c], fs1[c]);
                unsigned long long f2 = pack2(fs2[c], fs2[c]);
                acc1a = fma_f32x2(f1, wv.x, acc1a);
                acc1b = fma_f32x2(f1, wv.y, acc1b);
                acc2a = fma_f32x2(f2, wv.x, acc2a);
                acc2b = fma_f32x2(f2, wv.y, acc2b);
            }
            unsigned long long m1p = pack2(m1, m1), m2p = pack2(m2, m2);
            acc1a = mul_f32x2(acc1a, m1p);  acc1b = mul_f32x2(acc1b, m1p);
            acc2a = mul_f32x2(acc2a, m2p);  acc2b = mul_f32x2(acc2b, m2p);
            float e0, e1;
            unpack2(e0, e1, acc1a); a16[t  * 32 + o4 * 2]     = __floats2half2_rn(e0, e1);
            unpack2(e0, e1, acc1b); a16[t  * 32 + o4 * 2 + 1] = __floats2half2_rn(e0, e1);
            unpack2(e0, e1, acc2a); a16[t2 * 32 + o4 * 2]     = __floats2half2_rn(e0, e1);
            unpack2(e0, e1, acc2b); a16[t2 * 32 + o4 * 2 + 1] = __floats2half2_rn(e0, e1);
        }
    }
    __syncthreads();

    // ---- phase 4: fused LDS.64 gathers + PRMT idx; b' via f32x2; NO lrelu
    //      (monotone: max(0, max_t lrelu(h)) == max(0, max_t h)) ----
    {
        const int o4    = tid & 15;
        const int slice = tid >> 4;
        const uint2* a64 = reinterpret_cast<const uint2*>(s_ab);  // [TPTS][16] 8B
        const ulonglong2* wtb2 = reinterpret_cast<const ulonglong2*>(s_wtb);
        const __half2 hneg = __float2half2_rn(-60000.f);
        float4 rmax = make_float4(0.f, 0.f, 0.f, 0.f);
        for (int t = slice; t < nv; t += 16) {
            int t2 = t + 8;
            int t2c = (t2 < nv) ? t2 : t;
            const uint2 ia = *reinterpret_cast<const uint2*>(s_idx[t]);
            const uint2 ib = *reinterpret_cast<const uint2*>(s_idx[t2c]);
            __half2 ma0 = hneg, ma1 = hneg, mb0 = hneg, mb1 = hneg;
#pragma unroll
            for (int k = 0; k < KNN; k++) {
                unsigned wa = (k < 4) ? ia.x : ia.y;
                unsigned wb = (k < 4) ? ib.x : ib.y;
                int ja = (int)__byte_perm(wa, 0u, 0x4440u | (k & 3));
                int jb = (int)__byte_perm(wb, 0u, 0x4440u | (k & 3));
                uint2 pa = a64[ja * 16 + o4];
                uint2 pb = a64[jb * 16 + o4];
                ma0 = __hmax2(ma0, *reinterpret_cast<__half2*>(&pa.x));
                ma1 = __hmax2(ma1, *reinterpret_cast<__half2*>(&pa.y));
                mb0 = __hmax2(mb0, *reinterpret_cast<__half2*>(&pb.x));
                mb1 = __hmax2(mb1, *reinterpret_cast<__half2*>(&pb.y));
            }
            const float4 A1 = *reinterpret_cast<const float4*>(s_feat[t]);
            const float4 A2 = *reinterpret_cast<const float4*>(s_feat[t2c]);
            float fs1[4] = {A1.x, A1.y, A1.z, A1.w};
            float fs2[4] = {A2.x, A2.y, A2.z, A2.w};
            const float4 cb4 = *reinterpret_cast<const float4*>(&s_cb[o4 * 4]);
            unsigned long long b1a = pack2(cb4.x, cb4.y), b1b = pack2(cb4.z, cb4.w);
            unsigned long long b2a = b1a, b2b = b1b;
#pragma unroll
            for (int c = 0; c < 4; c++) {
                ulonglong2 wv = wtb2[c * 16 + o4];
                unsigned long long f1 = pack2(fs1[c], fs1[c]);
                unsigned long long f2 = pack2(fs2[c], fs2[c]);
                b1a = fma_f32x2(f1, wv.x, b1a);
                b1b = fma_f32x2(f1, wv.y, b1b);
                b2a = fma_f32x2(f2, wv.x, b2a);
                b2b = fma_f32x2(f2, wv.y, b2b);
            }
            float b1x, b1y, b1z, b1w, b2x, b2y, b2z, b2w;
            unpack2(b1x, b1y, b1a);  unpack2(b1z, b1w, b1b);
            unpack2(b2x, b2y, b2a);  unpack2(b2z, b2w, b2b);
            float2 fa0 = __half22float2(ma0), fa1 = __half22float2(ma1);
            float2 fb0 = __half22float2(mb0), fb1 = __half22float2(mb1);
            rmax.x = fmaxf(rmax.x, fmaxf(fa0.x + b1x, fb0.x + b2x));
            rmax.y = fmaxf(rmax.y, fmaxf(fa0.y + b1y, fb0.y + b2y));
            rmax.z = fmaxf(rmax.z, fmaxf(fa1.x + b1z, fb1.x + b2z));
            rmax.w = fmaxf(rmax.w, fmaxf(fa1.y + b1w, fb1.y + b2w));
        }
        // lanes xor-16 share o4 but hold the sibling slice: reduce in-warp
        rmax.x = fmaxf(rmax.x, __shfl_xor_sync(0xffffffffu, rmax.x, 16));
        rmax.y = fmaxf(rmax.y, __shfl_xor_sync(0xffffffffu, rmax.y, 16));
        rmax.z = fmaxf(rmax.z, __shfl_xor_sync(0xffffffffu, rmax.z, 16));
        rmax.w = fmaxf(rmax.w, __shfl_xor_sync(0xffffffffu, rmax.w, 16));
        if (lane < 16)
            reinterpret_cast<float4*>(s_scr)[warp * 16 + o4] = rmax;
    }
    __syncthreads();

    if (tid < 64) {
        float r = fmaxf(fmaxf(s_scr[tid], s_scr[64 + tid]),
                        fmaxf(s_scr[128 + tid], s_scr[192 + tid]));
        out[vox * 64 + tid] = r;
    }
}

extern "C" void kernel_launch(void* const* d_in, const int* in_sizes, int n_in,
                              void* d_out, int out_size) {
    const float* features   = (const float*)d_in[0];
    const float* conv_w     = (const float*)d_in[1];
    const float* bn_gamma   = (const float*)d_in[2];
    const float* bn_beta    = (const float*)d_in[3];
    const float* bn_mean    = (const float*)d_in[4];
    const float* bn_var     = (const float*)d_in[5];
    const int*   num_voxels = (const int*)d_in[6];
    const int*   coors      = (const int*)d_in[7];
    float*       out        = (float*)d_out;

    gcn_kernel<<<VOX, 128>>>(features, conv_w, bn_gamma, bn_beta, bn_mean, bn_var,
                             num_voxels, coors, out);
}